// round 3
// baseline (speedup 1.0000x reference)
#include <cuda_runtime.h>
#include <cstdint>

#define HWDIM 4096
#define CD    256
#define C8D   32
#define NB    4
#define QB    64
#define JB    64

typedef unsigned long long u64;
typedef unsigned int       u32;

// ---------------- scratch (no allocations allowed) ----------------
__device__ float g_q[(size_t)NB * HWDIM * C8D];   // [b][n][o]   2 MB
__device__ float g_k[(size_t)NB * C8D * HWDIM];   // [b][o][n]   2 MB
__device__ float g_v[(size_t)NB * HWDIM * CD];    // [b][n][c]  16 MB

// ---------------- f32x2 helpers (packed fp32 = full-rate FMA pipe) ----------------
__device__ __forceinline__ u64 ffma2(u64 a, u64 b, u64 c) {
    u64 d; asm("fma.rn.f32x2 %0, %1, %2, %3;" : "=l"(d) : "l"(a), "l"(b), "l"(c)); return d;
}
__device__ __forceinline__ u64 fmul2(u64 a, u64 b) {
    u64 d; asm("mul.rn.f32x2 %0, %1, %2;" : "=l"(d) : "l"(a), "l"(b)); return d;
}
__device__ __forceinline__ u64 pack2(float lo, float hi) {
    u64 d; asm("mov.b64 %0, {%1, %2};" : "=l"(d) : "f"(lo), "f"(hi)); return d;
}
__device__ __forceinline__ float f2lo(u64 v) { return __uint_as_float((u32)v); }
__device__ __forceinline__ float f2hi(u64 v) { return __uint_as_float((u32)(v >> 32)); }

// ---------------- cp.async ----------------
__device__ __forceinline__ void cp16(u32 dst, const void* src) {
    asm volatile("cp.async.cg.shared.global [%0], [%1], 16;" :: "r"(dst), "l"(src));
}
__device__ __forceinline__ void cp_commit() { asm volatile("cp.async.commit_group;"); }
template <int N>
__device__ __forceinline__ void cp_wait() { asm volatile("cp.async.wait_group %0;" :: "n"(N)); }

__device__ __forceinline__ u32 saddr(const void* p) {
    return (u32)__cvta_generic_to_shared(p);
}

// =====================================================================
// QK projection: q[b][n][o] = wq[o]·x[b][:][n] + bq ; k[b][o][n] likewise.
// CTA tile: 64 n × 64 o (o<32 -> q, o>=32 -> k). 256 threads, 4n×4o each.
// =====================================================================
__global__ __launch_bounds__(256) void qk_proj_kernel(
    const float* __restrict__ x,
    const float* __restrict__ wq, const float* __restrict__ bq,
    const float* __restrict__ wk, const float* __restrict__ bk)
{
    __shared__ float xs[64][65];   // [c][n]
    __shared__ float ws[64][66];   // [c][o]
    const int tid = threadIdx.x;
    const int b = blockIdx.y;
    const int n0 = blockIdx.x * 64;
    const int tx = tid & 15, ty = tid >> 4;

    u64 acc[4][2];
#pragma unroll
    for (int i = 0; i < 4; ++i) { acc[i][0] = 0ull; acc[i][1] = 0ull; }

    const float* xb = x + (size_t)b * CD * HWDIM;

    for (int c0 = 0; c0 < CD; c0 += 64) {
        __syncthreads();
#pragma unroll
        for (int it = 0; it < 16; ++it) {
            int idx = tid + it * 256;
            int cc = idx >> 6, nn = idx & 63;
            xs[cc][nn] = xb[(size_t)(c0 + cc) * HWDIM + n0 + nn];
        }
#pragma unroll
        for (int it = 0; it < 16; ++it) {
            int idx = tid + it * 256;
            int o = idx >> 6, cc = idx & 63;
            float wv = (o < 32) ? wq[o * CD + c0 + cc] : wk[(o - 32) * CD + c0 + cc];
            ws[cc][o] = wv;
        }
        __syncthreads();
#pragma unroll 8
        for (int kk = 0; kk < 64; ++kk) {
            u64 a0 = *(const u64*)&ws[kk][ty * 4];
            u64 a1 = *(const u64*)&ws[kk][ty * 4 + 2];
#pragma unroll
            for (int i = 0; i < 4; ++i) {
                float bv = xs[kk][tx * 4 + i];
                u64 bd = pack2(bv, bv);
                acc[i][0] = ffma2(a0, bd, acc[i][0]);
                acc[i][1] = ffma2(a1, bd, acc[i][1]);
            }
        }
    }
#pragma unroll
    for (int i = 0; i < 4; ++i) {
        int n = n0 + tx * 4 + i;
#pragma unroll
        for (int p = 0; p < 2; ++p) {
            int o = ty * 4 + 2 * p;
            float v0 = f2lo(acc[i][p]), v1 = f2hi(acc[i][p]);
            if (o < 32) {
                float* dq = g_q + ((size_t)b * HWDIM + n) * C8D;
                dq[o]     = v0 + bq[o];
                dq[o + 1] = v1 + bq[o + 1];
            } else {
                int ok = o - 32;
                g_k[((size_t)b * C8D + ok)     * HWDIM + n] = v0 + bk[ok];
                g_k[((size_t)b * C8D + ok + 1) * HWDIM + n] = v1 + bk[ok + 1];
            }
        }
    }
}

// =====================================================================
// V projection: v[b][n][c] = wv[c]·orig[b][:][n] + bv[c]
// Grid (64 n-tiles, 4 o-tiles, 4 b). Same micro-structure.
// =====================================================================
__global__ __launch_bounds__(256) void v_proj_kernel(
    const float* __restrict__ orig,
    const float* __restrict__ wv, const float* __restrict__ bv)
{
    __shared__ float xs[64][65];
    __shared__ float ws[64][66];
    const int tid = threadIdx.x;
    const int b = blockIdx.z;
    const int obase = blockIdx.y * 64;
    const int n0 = blockIdx.x * 64;
    const int tx = tid & 15, ty = tid >> 4;

    u64 acc[4][2];
#pragma unroll
    for (int i = 0; i < 4; ++i) { acc[i][0] = 0ull; acc[i][1] = 0ull; }

    const float* xb = orig + (size_t)b * CD * HWDIM;

    for (int c0 = 0; c0 < CD; c0 += 64) {
        __syncthreads();
#pragma unroll
        for (int it = 0; it < 16; ++it) {
            int idx = tid + it * 256;
            int cc = idx >> 6, nn = idx & 63;
            xs[cc][nn] = xb[(size_t)(c0 + cc) * HWDIM + n0 + nn];
        }
#pragma unroll
        for (int it = 0; it < 16; ++it) {
            int idx = tid + it * 256;
            int o = idx >> 6, cc = idx & 63;
            ws[cc][o] = wv[(size_t)(obase + o) * CD + c0 + cc];
        }
        __syncthreads();
#pragma unroll 8
        for (int kk = 0; kk < 64; ++kk) {
            u64 a0 = *(const u64*)&ws[kk][ty * 4];
            u64 a1 = *(const u64*)&ws[kk][ty * 4 + 2];
#pragma unroll
            for (int i = 0; i < 4; ++i) {
                float bv2 = xs[kk][tx * 4 + i];
                u64 bd = pack2(bv2, bv2);
                acc[i][0] = ffma2(a0, bd, acc[i][0]);
                acc[i][1] = ffma2(a1, bd, acc[i][1]);
            }
        }
    }
#pragma unroll
    for (int i = 0; i < 4; ++i) {
        int n = n0 + tx * 4 + i;
        float* dst = g_v + ((size_t)b * HWDIM + n) * CD + obase;
#pragma unroll
        for (int p = 0; p < 2; ++p) {
            int o = ty * 4 + 2 * p;
            dst[o]     = f2lo(acc[i][p]) + bv[obase + o];
            dst[o + 1] = f2hi(acc[i][p]) + bv[obase + o + 1];
        }
    }
}

// =====================================================================
// Flash attention. One CTA = 64 queries of one batch. 256 threads.
// smem layout (dynamic):
//   qs [64][33] f32        q tile
//   ks [32][68] f32        k tile (o-major, cp.async filled)
//   ss [64][66] f32        raw scores S
//   ps [64][65] u64        P duplicated as f32x2 (so phase C is pure LDS.64+FFMA2)
//   vs [64][256] f32 / Ost[256][65] f32 (union)
//   l_s[64], alpha_s[64]
// =====================================================================
#define QS_STR 33
#define KS_STR 68
#define SS_STR 66
#define PS_STR 65
#define VS_STR 256
#define OST_STR 65

#define QS_OFF 0
#define KS_OFF 8448
#define SS_OFF 17152
#define PS_OFF 34048
#define VS_OFF 67328
#define LS_OFF 133888
#define AL_OFF 134144
#define ATTN_SMEM 134400

__global__ __launch_bounds__(256, 1) void attn_kernel(
    const float* __restrict__ inp,
    const float* __restrict__ gamma_p,
    float* __restrict__ out)
{
    extern __shared__ char smem_raw[];
    float* qs      = (float*)(smem_raw + QS_OFF);
    float* ks      = (float*)(smem_raw + KS_OFF);
    float* ss      = (float*)(smem_raw + SS_OFF);
    u64*   ps      = (u64*)  (smem_raw + PS_OFF);
    float* vs      = (float*)(smem_raw + VS_OFF);
    float* Ost     = (float*)(smem_raw + VS_OFF);
    float* l_s     = (float*)(smem_raw + LS_OFF);
    float* alpha_s = (float*)(smem_raw + AL_OFF);

    const int tid = threadIdx.x;
    const int b = blockIdx.y;
    const int n0 = blockIdx.x * QB;
    const float gamma = gamma_p[0];

    const float* qg = g_q + ((size_t)b * HWDIM + n0) * C8D;
    const float* kg = g_k + (size_t)b * C8D * HWDIM;
    const float* vg = g_v + (size_t)b * HWDIM * CD;

    // load q tile once
    for (int idx = tid; idx < QB * C8D; idx += 256) {
        int q = idx >> 5, o = idx & 31;
        qs[q * QS_STR + o] = qg[q * C8D + o];
    }

    // role ids
    const int tx = tid & 15, ty = tid >> 4;        // phase A: 4q x 4j
    const int rB = tid >> 2, partB = tid & 3;      // phase B: row, quarter
    const int qq = tid >> 6;                       // phase C: q-quarter (16 q)
    const int cp = tid & 63;                       // phase C: channel pairs cp, cp+64

    float m_row = -1e30f, l_row = 0.0f;

    u64 acc[16][2];
#pragma unroll
    for (int q = 0; q < 16; ++q) { acc[q][0] = 0ull; acc[q][1] = 0ull; }

    const u32 ks_u = saddr(ks);
    const u32 vs_u = saddr(vs);

    for (int t = 0; t < HWDIM / JB; ++t) {
        const int j0 = t * JB;
        __syncthreads();   // previous tile's phase C fully done (vs/ps/ks reusable)

        // async load K tile: 32 rows x 64 floats
        {
            int idx = tid;
#pragma unroll
            for (int it = 0; it < 2; ++it, idx += 256) {
                int o = idx >> 4, ch = idx & 15;
                cp16(ks_u + (u32)(o * KS_STR + ch * 4) * 4,
                     kg + (size_t)o * HWDIM + j0 + ch * 4);
            }
        }
        cp_commit();
        // async load V tile: 64 rows x 256 floats
        {
            int idx = tid;
#pragma unroll
            for (int it = 0; it < 16; ++it, idx += 256) {
                int jj = idx >> 6, ch = idx & 63;
                cp16(vs_u + (u32)(jj * VS_STR + ch * 4) * 4,
                     vg + (size_t)(j0 + jj) * CD + ch * 4);
            }
        }
        cp_commit();

        cp_wait<1>();      // K tile done (V still streaming)
        __syncthreads();

        // ---- phase A: S = Q K^T (f32x2 over j-pairs) ----
        {
            u64 s[4][2];
#pragma unroll
            for (int qi = 0; qi < 4; ++qi) { s[qi][0] = 0ull; s[qi][1] = 0ull; }
#pragma unroll 8
            for (int o = 0; o < 32; ++o) {
                u64 k0 = *(const u64*)&ks[o * KS_STR + tx * 4];
                u64 k1 = *(const u64*)&ks[o * KS_STR + tx * 4 + 2];
#pragma unroll
                for (int qi = 0; qi < 4; ++qi) {
                    float qv = qs[(ty * 4 + qi) * QS_STR + o];
                    u64 qd = pack2(qv, qv);
                    s[qi][0] = ffma2(qd, k0, s[qi][0]);
                    s[qi][1] = ffma2(qd, k1, s[qi][1]);
                }
            }
#pragma unroll
            for (int qi = 0; qi < 4; ++qi) {
                int row = ty * 4 + qi;
                *(u64*)&ss[row * SS_STR + tx * 4]     = s[qi][0];
                *(u64*)&ss[row * SS_STR + tx * 4 + 2] = s[qi][1];
            }
        }
        __syncthreads();

        // ---- phase B: online softmax over this key tile ----
        {
            float sv[16];
            const int base = rB * SS_STR + partB * 16;
#pragma unroll
            for (int i = 0; i < 16; ++i) sv[i] = ss[base + i];
            float mx = sv[0];
#pragma unroll
            for (int i = 1; i < 16; ++i) mx = fmaxf(mx, sv[i]);
            mx = fmaxf(mx, __shfl_xor_sync(0xffffffffu, mx, 1));
            mx = fmaxf(mx, __shfl_xor_sync(0xffffffffu, mx, 2));
            float m_new = fmaxf(m_row, mx);
            float alpha = __expf(m_row - m_new);
            float sum = 0.0f;
#pragma unroll
            for (int i = 0; i < 16; ++i) {
                float p = __expf(sv[i] - m_new);
                sum += p;
                ps[rB * PS_STR + partB * 16 + i] = pack2(p, p);
            }
            sum += __shfl_xor_sync(0xffffffffu, sum, 1);
            sum += __shfl_xor_sync(0xffffffffu, sum, 2);
            l_row = l_row * alpha + sum;
            m_row = m_new;
            if (partB == 0) { alpha_s[rB] = alpha; l_s[rB] = l_row; }
        }
        cp_wait<0>();      // V tile done
        __syncthreads();

        // ---- phase C: O = alpha*O + P V (FFMA2-bound, 2 FFMA2 per LDS.64) ----
        {
#pragma unroll
            for (int q = 0; q < 16; ++q) {
                float a = alpha_s[qq * 16 + q];
                u64 ad = pack2(a, a);
                acc[q][0] = fmul2(acc[q][0], ad);
                acc[q][1] = fmul2(acc[q][1], ad);
            }
#pragma unroll 2
            for (int j = 0; j < JB; ++j) {
                u64 v0 = *(const u64*)&vs[j * VS_STR + 2 * cp];
                u64 v1 = *(const u64*)&vs[j * VS_STR + 2 * cp + 128];
#pragma unroll
                for (int q = 0; q < 16; ++q) {
                    u64 p = ps[(qq * 16 + q) * PS_STR + j];
                    acc[q][0] = ffma2(p, v0, acc[q][0]);
                    acc[q][1] = ffma2(p, v1, acc[q][1]);
                }
            }
        }
    }

    __syncthreads();   // vs free -> reuse as Ost; l_s final
    {
#pragma unroll
        for (int q = 0; q < 16; ++q) {
            int qi = qq * 16 + q;
            float sc = gamma / l_s[qi];
            Ost[(2 * cp)       * OST_STR + qi] = f2lo(acc[q][0]) * sc;
            Ost[(2 * cp + 1)   * OST_STR + qi] = f2hi(acc[q][0]) * sc;
            Ost[(2 * cp + 128) * OST_STR + qi] = f2lo(acc[q][1]) * sc;
            Ost[(2 * cp + 129) * OST_STR + qi] = f2hi(acc[q][1]) * sc;
        }
    }
    __syncthreads();
    {
        const float* ib = inp + (size_t)b * CD * HWDIM + n0;
        float* ob = out + (size_t)b * CD * HWDIM + n0;
        for (int idx = tid; idx < CD * QB; idx += 256) {
            int c = idx >> 6, q = idx & 63;
            ob[(size_t)c * HWDIM + q] = Ost[c * OST_STR + q] + ib[(size_t)c * HWDIM + q];
        }
    }
}

// =====================================================================
extern "C" void kernel_launch(void* const* d_in, const int* in_sizes, int n_in,
                              void* d_out, int out_size)
{
    (void)in_sizes; (void)n_in; (void)out_size;
    const float* input    = (const float*)d_in[0];
    const float* original = (const float*)d_in[1];
    const float* wq    = (const float*)d_in[2];
    const float* bq    = (const float*)d_in[3];
    const float* wk    = (const float*)d_in[4];
    const float* bk    = (const float*)d_in[5];
    const float* wv    = (const float*)d_in[6];
    const float* bv    = (const float*)d_in[7];
    const float* gamma = (const float*)d_in[8];
    float* out = (float*)d_out;

    cudaFuncSetAttribute(attn_kernel, cudaFuncAttributeMaxDynamicSharedMemorySize, ATTN_SMEM);

    qk_proj_kernel<<<dim3(HWDIM / 64, NB), 256>>>(input, wq, bq, wk, bk);
    v_proj_kernel<<<dim3(HWDIM / 64, CD / 64, NB), 256>>>(original, wv, bv);
    attn_kernel<<<dim3(HWDIM / QB, NB), 256, ATTN_SMEM>>>(input, gamma, out);
}

// round 4
// speedup vs baseline: 1.0059x; 1.0059x over previous
#include <cuda_runtime.h>
#include <cstdint>

#define HWDIM 4096
#define CD    256
#define C8D   32
#define NB    4
#define QB    64
#define JB    64

typedef unsigned long long u64;
typedef unsigned int       u32;

// ---------------- scratch (no allocations allowed) ----------------
__device__ float g_q[(size_t)NB * HWDIM * C8D];   // [b][n][o]   2 MB
__device__ float g_k[(size_t)NB * C8D * HWDIM];   // [b][o][n]   2 MB
__device__ float g_v[(size_t)NB * HWDIM * CD];    // [b][n][c]  16 MB

// ---------------- f32x2 helpers (packed fp32 = full-rate FMA pipe) ----------------
__device__ __forceinline__ u64 ffma2(u64 a, u64 b, u64 c) {
    u64 d; asm("fma.rn.f32x2 %0, %1, %2, %3;" : "=l"(d) : "l"(a), "l"(b), "l"(c)); return d;
}
__device__ __forceinline__ u64 fmul2(u64 a, u64 b) {
    u64 d; asm("mul.rn.f32x2 %0, %1, %2;" : "=l"(d) : "l"(a), "l"(b)); return d;
}
__device__ __forceinline__ u64 pack2(float lo, float hi) {
    u64 d; asm("mov.b64 %0, {%1, %2};" : "=l"(d) : "f"(lo), "f"(hi)); return d;
}
__device__ __forceinline__ float f2lo(u64 v) { return __uint_as_float((u32)v); }
__device__ __forceinline__ float f2hi(u64 v) { return __uint_as_float((u32)(v >> 32)); }

// ---------------- cp.async ----------------
__device__ __forceinline__ void cp16(u32 dst, const void* src) {
    asm volatile("cp.async.cg.shared.global [%0], [%1], 16;" :: "r"(dst), "l"(src));
}
__device__ __forceinline__ void cp_commit() { asm volatile("cp.async.commit_group;"); }
template <int N>
__device__ __forceinline__ void cp_wait() { asm volatile("cp.async.wait_group %0;" :: "n"(N)); }

__device__ __forceinline__ u32 saddr(const void* p) {
    return (u32)__cvta_generic_to_shared(p);
}

// =====================================================================
// QK projection: q[b][n][o] = wq[o]·x[b][:][n] + bq ; k[b][o][n] likewise.
// CTA tile: 64 n × 64 o (o<32 -> q, o>=32 -> k). 256 threads, 4n×4o each.
// =====================================================================
__global__ __launch_bounds__(256) void qk_proj_kernel(
    const float* __restrict__ x,
    const float* __restrict__ wq, const float* __restrict__ bq,
    const float* __restrict__ wk, const float* __restrict__ bk)
{
    __shared__ float xs[64][65];   // [c][n]
    __shared__ float ws[64][66];   // [c][o]
    const int tid = threadIdx.x;
    const int b = blockIdx.y;
    const int n0 = blockIdx.x * 64;
    const int tx = tid & 15, ty = tid >> 4;

    u64 acc[4][2];
#pragma unroll
    for (int i = 0; i < 4; ++i) { acc[i][0] = 0ull; acc[i][1] = 0ull; }

    const float* xb = x + (size_t)b * CD * HWDIM;

    for (int c0 = 0; c0 < CD; c0 += 64) {
        __syncthreads();
#pragma unroll
        for (int it = 0; it < 16; ++it) {
            int idx = tid + it * 256;
            int cc = idx >> 6, nn = idx & 63;
            xs[cc][nn] = xb[(size_t)(c0 + cc) * HWDIM + n0 + nn];
        }
#pragma unroll
        for (int it = 0; it < 16; ++it) {
            int idx = tid + it * 256;
            int o = idx >> 6, cc = idx & 63;
            float wv = (o < 32) ? wq[o * CD + c0 + cc] : wk[(o - 32) * CD + c0 + cc];
            ws[cc][o] = wv;
        }
        __syncthreads();
#pragma unroll 8
        for (int kk = 0; kk < 64; ++kk) {
            u64 a0 = *(const u64*)&ws[kk][ty * 4];
            u64 a1 = *(const u64*)&ws[kk][ty * 4 + 2];
#pragma unroll
            for (int i = 0; i < 4; ++i) {
                float bv = xs[kk][tx * 4 + i];
                u64 bd = pack2(bv, bv);
                acc[i][0] = ffma2(a0, bd, acc[i][0]);
                acc[i][1] = ffma2(a1, bd, acc[i][1]);
            }
        }
    }
#pragma unroll
    for (int i = 0; i < 4; ++i) {
        int n = n0 + tx * 4 + i;
#pragma unroll
        for (int p = 0; p < 2; ++p) {
            int o = ty * 4 + 2 * p;
            float v0 = f2lo(acc[i][p]), v1 = f2hi(acc[i][p]);
            if (o < 32) {
                float* dq = g_q + ((size_t)b * HWDIM + n) * C8D;
                dq[o]     = v0 + bq[o];
                dq[o + 1] = v1 + bq[o + 1];
            } else {
                int ok = o - 32;
                g_k[((size_t)b * C8D + ok)     * HWDIM + n] = v0 + bk[ok];
                g_k[((size_t)b * C8D + ok + 1) * HWDIM + n] = v1 + bk[ok + 1];
            }
        }
    }
}

// =====================================================================
// V projection: v[b][n][c] = wv[c]·orig[b][:][n] + bv[c]
// Grid (64 n-tiles, 4 o-tiles, 4 b). Same micro-structure.
// =====================================================================
__global__ __launch_bounds__(256) void v_proj_kernel(
    const float* __restrict__ orig,
    const float* __restrict__ wv, const float* __restrict__ bv)
{
    __shared__ float xs[64][65];
    __shared__ float ws[64][66];
    const int tid = threadIdx.x;
    const int b = blockIdx.z;
    const int obase = blockIdx.y * 64;
    const int n0 = blockIdx.x * 64;
    const int tx = tid & 15, ty = tid >> 4;

    u64 acc[4][2];
#pragma unroll
    for (int i = 0; i < 4; ++i) { acc[i][0] = 0ull; acc[i][1] = 0ull; }

    const float* xb = orig + (size_t)b * CD * HWDIM;

    for (int c0 = 0; c0 < CD; c0 += 64) {
        __syncthreads();
#pragma unroll
        for (int it = 0; it < 16; ++it) {
            int idx = tid + it * 256;
            int cc = idx >> 6, nn = idx & 63;
            xs[cc][nn] = xb[(size_t)(c0 + cc) * HWDIM + n0 + nn];
        }
#pragma unroll
        for (int it = 0; it < 16; ++it) {
            int idx = tid + it * 256;
            int o = idx >> 6, cc = idx & 63;
            ws[cc][o] = wv[(size_t)(obase + o) * CD + c0 + cc];
        }
        __syncthreads();
#pragma unroll 8
        for (int kk = 0; kk < 64; ++kk) {
            u64 a0 = *(const u64*)&ws[kk][ty * 4];
            u64 a1 = *(const u64*)&ws[kk][ty * 4 + 2];
#pragma unroll
            for (int i = 0; i < 4; ++i) {
                float bv2 = xs[kk][tx * 4 + i];
                u64 bd = pack2(bv2, bv2);
                acc[i][0] = ffma2(a0, bd, acc[i][0]);
                acc[i][1] = ffma2(a1, bd, acc[i][1]);
            }
        }
    }
#pragma unroll
    for (int i = 0; i < 4; ++i) {
        int n = n0 + tx * 4 + i;
        float* dst = g_v + ((size_t)b * HWDIM + n) * CD + obase;
#pragma unroll
        for (int p = 0; p < 2; ++p) {
            int o = ty * 4 + 2 * p;
            dst[o]     = f2lo(acc[i][p]) + bv[obase + o];
            dst[o + 1] = f2hi(acc[i][p]) + bv[obase + o + 1];
        }
    }
}

// =====================================================================
// Flash attention. One CTA = 64 queries of one batch. 256 threads.
// smem layout (dynamic):
//   qs [64][33] f32        q tile
//   ks [32][68] f32        k tile (o-major, cp.async filled)
//   ss [64][66] f32        raw scores S
//   ps [64][65] u64        P duplicated as f32x2 (so phase C is pure LDS.64+FFMA2)
//   vs [64][256] f32 / Ost[256][65] f32 (union)
//   l_s[64], alpha_s[64]
// =====================================================================
#define QS_STR 33
#define KS_STR 68
#define SS_STR 66
#define PS_STR 65
#define VS_STR 256
#define OST_STR 65

#define QS_OFF 0
#define KS_OFF 8448
#define SS_OFF 17152
#define PS_OFF 34048
#define VS_OFF 67328
#define LS_OFF 133888
#define AL_OFF 134144
#define ATTN_SMEM 134400

__global__ __launch_bounds__(256, 1) void attn_kernel(
    const float* __restrict__ inp,
    const float* __restrict__ gamma_p,
    float* __restrict__ out)
{
    extern __shared__ char smem_raw[];
    float* qs      = (float*)(smem_raw + QS_OFF);
    float* ks      = (float*)(smem_raw + KS_OFF);
    float* ss      = (float*)(smem_raw + SS_OFF);
    u64*   ps      = (u64*)  (smem_raw + PS_OFF);
    float* vs      = (float*)(smem_raw + VS_OFF);
    float* Ost     = (float*)(smem_raw + VS_OFF);
    float* l_s     = (float*)(smem_raw + LS_OFF);
    float* alpha_s = (float*)(smem_raw + AL_OFF);

    const int tid = threadIdx.x;
    const int b = blockIdx.y;
    const int n0 = blockIdx.x * QB;
    const float gamma = gamma_p[0];

    const float* qg = g_q + ((size_t)b * HWDIM + n0) * C8D;
    const float* kg = g_k + (size_t)b * C8D * HWDIM;
    const float* vg = g_v + (size_t)b * HWDIM * CD;

    // load q tile once
    for (int idx = tid; idx < QB * C8D; idx += 256) {
        int q = idx >> 5, o = idx & 31;
        qs[q * QS_STR + o] = qg[q * C8D + o];
    }

    // role ids
    const int tx = tid & 15, ty = tid >> 4;        // phase A: 4q x 4j
    const int rB = tid >> 2, partB = tid & 3;      // phase B: row, quarter
    const int qq = tid >> 6;                       // phase C: q-quarter (16 q)
    const int cp = tid & 63;                       // phase C: channel pairs cp, cp+64

    float m_row = -1e30f, l_row = 0.0f;

    u64 acc[16][2];
#pragma unroll
    for (int q = 0; q < 16; ++q) { acc[q][0] = 0ull; acc[q][1] = 0ull; }

    const u32 ks_u = saddr(ks);
    const u32 vs_u = saddr(vs);

    for (int t = 0; t < HWDIM / JB; ++t) {
        const int j0 = t * JB;
        __syncthreads();   // previous tile's phase C fully done (vs/ps/ks reusable)

        // async load K tile: 32 rows x 64 floats
        {
            int idx = tid;
#pragma unroll
            for (int it = 0; it < 2; ++it, idx += 256) {
                int o = idx >> 4, ch = idx & 15;
                cp16(ks_u + (u32)(o * KS_STR + ch * 4) * 4,
                     kg + (size_t)o * HWDIM + j0 + ch * 4);
            }
        }
        cp_commit();
        // async load V tile: 64 rows x 256 floats
        {
            int idx = tid;
#pragma unroll
            for (int it = 0; it < 16; ++it, idx += 256) {
                int jj = idx >> 6, ch = idx & 63;
                cp16(vs_u + (u32)(jj * VS_STR + ch * 4) * 4,
                     vg + (size_t)(j0 + jj) * CD + ch * 4);
            }
        }
        cp_commit();

        cp_wait<1>();      // K tile done (V still streaming)
        __syncthreads();

        // ---- phase A: S = Q K^T (f32x2 over j-pairs) ----
        {
            u64 s[4][2];
#pragma unroll
            for (int qi = 0; qi < 4; ++qi) { s[qi][0] = 0ull; s[qi][1] = 0ull; }
#pragma unroll 8
            for (int o = 0; o < 32; ++o) {
                u64 k0 = *(const u64*)&ks[o * KS_STR + tx * 4];
                u64 k1 = *(const u64*)&ks[o * KS_STR + tx * 4 + 2];
#pragma unroll
                for (int qi = 0; qi < 4; ++qi) {
                    float qv = qs[(ty * 4 + qi) * QS_STR + o];
                    u64 qd = pack2(qv, qv);
                    s[qi][0] = ffma2(qd, k0, s[qi][0]);
                    s[qi][1] = ffma2(qd, k1, s[qi][1]);
                }
            }
#pragma unroll
            for (int qi = 0; qi < 4; ++qi) {
                int row = ty * 4 + qi;
                *(u64*)&ss[row * SS_STR + tx * 4]     = s[qi][0];
                *(u64*)&ss[row * SS_STR + tx * 4 + 2] = s[qi][1];
            }
        }
        __syncthreads();

        // ---- phase B: online softmax over this key tile ----
        {
            float sv[16];
            const int base = rB * SS_STR + partB * 16;
#pragma unroll
            for (int i = 0; i < 16; ++i) sv[i] = ss[base + i];
            float mx = sv[0];
#pragma unroll
            for (int i = 1; i < 16; ++i) mx = fmaxf(mx, sv[i]);
            mx = fmaxf(mx, __shfl_xor_sync(0xffffffffu, mx, 1));
            mx = fmaxf(mx, __shfl_xor_sync(0xffffffffu, mx, 2));
            float m_new = fmaxf(m_row, mx);
            float alpha = __expf(m_row - m_new);
            float sum = 0.0f;
#pragma unroll
            for (int i = 0; i < 16; ++i) {
                float p = __expf(sv[i] - m_new);
                sum += p;
                ps[rB * PS_STR + partB * 16 + i] = pack2(p, p);
            }
            sum += __shfl_xor_sync(0xffffffffu, sum, 1);
            sum += __shfl_xor_sync(0xffffffffu, sum, 2);
            l_row = l_row * alpha + sum;
            m_row = m_new;
            if (partB == 0) { alpha_s[rB] = alpha; l_s[rB] = l_row; }
        }
        cp_wait<0>();      // V tile done
        __syncthreads();

        // ---- phase C: O = alpha*O + P V (FFMA2-bound, 2 FFMA2 per LDS.64) ----
        {
#pragma unroll
            for (int q = 0; q < 16; ++q) {
                float a = alpha_s[qq * 16 + q];
                u64 ad = pack2(a, a);
                acc[q][0] = fmul2(acc[q][0], ad);
                acc[q][1] = fmul2(acc[q][1], ad);
            }
#pragma unroll 2
            for (int j = 0; j < JB; ++j) {
                u64 v0 = *(const u64*)&vs[j * VS_STR + 2 * cp];
                u64 v1 = *(const u64*)&vs[j * VS_STR + 2 * cp + 128];
#pragma unroll
                for (int q = 0; q < 16; ++q) {
                    u64 p = ps[(qq * 16 + q) * PS_STR + j];
                    acc[q][0] = ffma2(p, v0, acc[q][0]);
                    acc[q][1] = ffma2(p, v1, acc[q][1]);
                }
            }
        }
    }

    __syncthreads();   // vs free -> reuse as Ost; l_s final
    {
#pragma unroll
        for (int q = 0; q < 16; ++q) {
            int qi = qq * 16 + q;
            float sc = gamma / l_s[qi];
            Ost[(2 * cp)       * OST_STR + qi] = f2lo(acc[q][0]) * sc;
            Ost[(2 * cp + 1)   * OST_STR + qi] = f2hi(acc[q][0]) * sc;
            Ost[(2 * cp + 128) * OST_STR + qi] = f2lo(acc[q][1]) * sc;
            Ost[(2 * cp + 129) * OST_STR + qi] = f2hi(acc[q][1]) * sc;
        }
    }
    __syncthreads();
    {
        const float* ib = inp + (size_t)b * CD * HWDIM + n0;
        float* ob = out + (size_t)b * CD * HWDIM + n0;
        for (int idx = tid; idx < CD * QB; idx += 256) {
            int c = idx >> 6, q = idx & 63;
            ob[(size_t)c * HWDIM + q] = Ost[c * OST_STR + q] + ib[(size_t)c * HWDIM + q];
        }
    }
}

// =====================================================================
extern "C" void kernel_launch(void* const* d_in, const int* in_sizes, int n_in,
                              void* d_out, int out_size)
{
    (void)in_sizes; (void)n_in; (void)out_size;
    const float* input    = (const float*)d_in[0];
    const float* original = (const float*)d_in[1];
    const float* wq    = (const float*)d_in[2];
    const float* bq    = (const float*)d_in[3];
    const float* wk    = (const float*)d_in[4];
    const float* bk    = (const float*)d_in[5];
    const float* wv    = (const float*)d_in[6];
    const float* bv    = (const float*)d_in[7];
    const float* gamma = (const float*)d_in[8];
    float* out = (float*)d_out;

    cudaFuncSetAttribute(attn_kernel, cudaFuncAttributeMaxDynamicSharedMemorySize, ATTN_SMEM);

    qk_proj_kernel<<<dim3(HWDIM / 64, NB), 256>>>(input, wq, bq, wk, bk);
    v_proj_kernel<<<dim3(HWDIM / 64, CD / 64, NB), 256>>>(original, wv, bv);
    attn_kernel<<<dim3(HWDIM / QB, NB), 256, ATTN_SMEM>>>(input, gamma, out);
}

// round 6
// speedup vs baseline: 2.4058x; 2.3916x over previous
#include <cuda_runtime.h>
#include <cuda_bf16.h>
#include <cstdint>

typedef unsigned long long u64;
typedef unsigned int       u32;

#define HWDIM 4096
#define CD    256
#define NB    4
#define NTILE 64

// ---------------- scratch (no allocations allowed) ----------------
__device__ __nv_bfloat16 g_qhl[(size_t)NB * HWDIM * 64];   // [b][n][Qh(32)|Ql(32)]
__device__ __nv_bfloat16 g_khl[(size_t)NB * HWDIM * 64];   // [b][n][Kh|Kl]
__device__ __nv_bfloat16 g_vh[(size_t)NB * CD * HWDIM];    // [b][c][n]
__device__ __nv_bfloat16 g_vl[(size_t)NB * CD * HWDIM];

// ---------------- helpers ----------------
__device__ __forceinline__ u32 saddr(const void* p) { return (u32)__cvta_generic_to_shared(p); }
__device__ __forceinline__ void cp16(u32 dst, const void* src) {
    asm volatile("cp.async.cg.shared.global [%0], [%1], 16;" :: "r"(dst), "l"(src));
}
__device__ __forceinline__ void cp_commit() { asm volatile("cp.async.commit_group;" ::: "memory"); }
__device__ __forceinline__ void cp_wait0()  { asm volatile("cp.async.wait_group 0;" ::: "memory"); }

__device__ __forceinline__ u32 bf2(float lo, float hi) {
    u32 r; asm("cvt.rn.bf16x2.f32 %0, %1, %2;" : "=r"(r) : "f"(hi), "f"(lo)); return r;
}
__device__ __forceinline__ u64 pk64(u32 lo, u32 hi) {
    u64 r; asm("mov.b64 %0, {%1, %2};" : "=l"(r) : "r"(lo), "r"(hi)); return r;
}
__device__ __forceinline__ float lo16f(u32 h) { return __uint_as_float(h << 16); }
__device__ __forceinline__ float hi16f(u32 h) { return __uint_as_float(h & 0xFFFF0000u); }
__device__ __forceinline__ float f2lo(u64 v) { return __uint_as_float((u32)v); }
__device__ __forceinline__ float f2hi(u64 v) { return __uint_as_float((u32)(v >> 32)); }
__device__ __forceinline__ u64 ffma2(u64 a, u64 b, u64 c) {
    u64 d; asm("fma.rn.f32x2 %0, %1, %2, %3;" : "=l"(d) : "l"(a), "l"(b), "l"(c)); return d;
}
__device__ __forceinline__ u64 pack2(float lo, float hi) {
    u64 d; asm("mov.b64 %0, {%1, %2};" : "=l"(d) : "f"(lo), "f"(hi)); return d;
}

// ldmatrix x4 (non-trans): matrices from lane-groups 0-7/8-15/16-23/24-31
#define LDSM4(r, a) \
    asm volatile("ldmatrix.sync.aligned.m8n8.x4.shared.b16 {%0,%1,%2,%3}, [%4];" \
        : "=r"((r)[0]), "=r"((r)[1]), "=r"((r)[2]), "=r"((r)[3]) : "r"(a))

// D += A * B  (m16n8k16, bf16 in, f32 accum)
#define MMA(d, a, b0_, b1_) \
    asm volatile("mma.sync.aligned.m16n8k16.row.col.f32.bf16.bf16.f32 " \
        "{%0,%1,%2,%3}, {%4,%5,%6,%7}, {%8,%9}, {%0,%1,%2,%3};" \
        : "+f"((d)[0]), "+f"((d)[1]), "+f"((d)[2]), "+f"((d)[3]) \
        : "r"((a)[0]), "r"((a)[1]), "r"((a)[2]), "r"((a)[3]), "r"(b0_), "r"(b1_))

// =====================================================================
// QK projection (fp32 FFMA2) -> bf16 hi/lo splits [b][n][Qh|Ql]/[Kh|Kl]
// =====================================================================
__global__ __launch_bounds__(256) void qk_proj_kernel(
    const float* __restrict__ x,
    const float* __restrict__ wq, const float* __restrict__ bq,
    const float* __restrict__ wk, const float* __restrict__ bk)
{
    __shared__ float xs[64][65];
    __shared__ float ws[64][66];
    const int tid = threadIdx.x;
    const int b = blockIdx.y;
    const int n0 = blockIdx.x * 64;
    const int tx = tid & 15, ty = tid >> 4;

    u64 acc[4][2];
#pragma unroll
    for (int i = 0; i < 4; ++i) { acc[i][0] = 0ull; acc[i][1] = 0ull; }

    const float* xb = x + (size_t)b * CD * HWDIM;

    for (int c0 = 0; c0 < CD; c0 += 64) {
        __syncthreads();
#pragma unroll
        for (int it = 0; it < 16; ++it) {
            int idx = tid + it * 256;
            int cc = idx >> 6, nn = idx & 63;
            xs[cc][nn] = xb[(size_t)(c0 + cc) * HWDIM + n0 + nn];
        }
#pragma unroll
        for (int it = 0; it < 16; ++it) {
            int idx = tid + it * 256;
            int o = idx >> 6, cc = idx & 63;
            ws[cc][o] = (o < 32) ? wq[o * CD + c0 + cc] : wk[(o - 32) * CD + c0 + cc];
        }
        __syncthreads();
#pragma unroll 8
        for (int kk = 0; kk < 64; ++kk) {
            u64 a0 = *(const u64*)&ws[kk][ty * 4];
            u64 a1 = *(const u64*)&ws[kk][ty * 4 + 2];
#pragma unroll
            for (int i = 0; i < 4; ++i) {
                float bv2 = xs[kk][tx * 4 + i];
                u64 bd = pack2(bv2, bv2);
                acc[i][0] = ffma2(a0, bd, acc[i][0]);
                acc[i][1] = ffma2(a1, bd, acc[i][1]);
            }
        }
    }
    const int og = ty * 4;
    float bb0, bb1, bb2, bb3;
    if (ty < 8) { bb0 = bq[og]; bb1 = bq[og + 1]; bb2 = bq[og + 2]; bb3 = bq[og + 3]; }
    else        { bb0 = bk[og - 32]; bb1 = bk[og - 31]; bb2 = bk[og - 30]; bb3 = bk[og - 29]; }
    __nv_bfloat16* arr = (ty < 8) ? g_qhl : g_khl;
    const int ol = (ty < 8) ? og : og - 32;
#pragma unroll
    for (int i = 0; i < 4; ++i) {
        int n = n0 + tx * 4 + i;
        float f0 = f2lo(acc[i][0]) + bb0;
        float f1 = f2hi(acc[i][0]) + bb1;
        float f2 = f2lo(acc[i][1]) + bb2;
        float f3 = f2hi(acc[i][1]) + bb3;
        u32 h01 = bf2(f0, f1), h23 = bf2(f2, f3);
        u32 l01 = bf2(f0 - lo16f(h01), f1 - hi16f(h01));
        u32 l23 = bf2(f2 - lo16f(h23), f3 - hi16f(h23));
        __nv_bfloat16* base = arr + ((size_t)b * HWDIM + n) * 64 + ol;
        *(u64*)base        = pk64(h01, h23);
        *(u64*)(base + 32) = pk64(l01, l23);
    }
}

// =====================================================================
// V projection -> g_vh/g_vl [b][c][n] bf16 splits.
// =====================================================================
__global__ __launch_bounds__(256) void v_proj_kernel(
    const float* __restrict__ orig,
    const float* __restrict__ wv, const float* __restrict__ bv)
{
    __shared__ float xs[64][65];
    __shared__ float ws[64][66];
    const int tid = threadIdx.x;
    const int b = blockIdx.z;
    const int obase = blockIdx.y * 64;
    const int n0 = blockIdx.x * 64;
    const int tx = tid & 15, ty = tid >> 4;

    u64 acc[4][2];
#pragma unroll
    for (int i = 0; i < 4; ++i) { acc[i][0] = 0ull; acc[i][1] = 0ull; }

    const float* xb = orig + (size_t)b * CD * HWDIM;

    for (int c0 = 0; c0 < CD; c0 += 64) {
        __syncthreads();
#pragma unroll
        for (int it = 0; it < 16; ++it) {
            int idx = tid + it * 256;
            int cc = idx >> 6, nn = idx & 63;
            xs[cc][nn] = xb[(size_t)(c0 + cc) * HWDIM + n0 + nn];
        }
#pragma unroll
        for (int it = 0; it < 16; ++it) {
            int idx = tid + it * 256;
            int o = idx >> 6, cc = idx & 63;
            ws[cc][o] = wv[(size_t)(obase + o) * CD + c0 + cc];
        }
        __syncthreads();
#pragma unroll 8
        for (int kk = 0; kk < 64; ++kk) {
            u64 a0 = *(const u64*)&ws[kk][ty * 4];
            u64 a1 = *(const u64*)&ws[kk][ty * 4 + 2];
#pragma unroll
            for (int i = 0; i < 4; ++i) {
                float bv2 = xs[kk][tx * 4 + i];
                u64 bd = pack2(bv2, bv2);
                acc[i][0] = ffma2(a0, bd, acc[i][0]);
                acc[i][1] = ffma2(a1, bd, acc[i][1]);
            }
        }
    }
#pragma unroll
    for (int ol = 0; ol < 4; ++ol) {
        int c = obase + ty * 4 + ol;
        float bb = bv[c];
        float f[4];
#pragma unroll
        for (int i = 0; i < 4; ++i) {
            u64 a = acc[i][ol >> 1];
            f[i] = ((ol & 1) ? f2hi(a) : f2lo(a)) + bb;
        }
        u32 h01 = bf2(f[0], f[1]), h23 = bf2(f[2], f[3]);
        u32 l01 = bf2(f[0] - lo16f(h01), f[1] - hi16f(h01));
        u32 l23 = bf2(f[2] - lo16f(h23), f[3] - hi16f(h23));
        size_t off = ((size_t)b * CD + c) * HWDIM + n0 + tx * 4;
        *(u64*)(g_vh + off) = pk64(h01, h23);
        *(u64*)(g_vl + off) = pk64(l01, l23);
    }
}

// =====================================================================
// Flash attention via mma.sync m16n8k16 bf16, 3-term compensated.
// 256 threads (8 warps); warp = 16 q x 128 c; CTA = 64 q; grid (64, 4).
// smem rows padded to 144 B -> conflict-free ldmatrix.
// =====================================================================
#define SQ   0u
#define SK   9216u          // 2 bufs x 64 x 144
#define SKB  9216u
#define SV   27648u         // 2 bufs x (hi 256x144 | lo 256x144)
#define SVB  73728u
#define SVLO 36864u
#define LSOFF 175104u
#define ATTN_SMEM 175616

__device__ __forceinline__ void load_kv_tile(u32 sb, int buf, int j0, int tid,
    const __nv_bfloat16* kg, const __nv_bfloat16* vh, const __nv_bfloat16* vl)
{
    u32 kd = sb + SK + (u32)buf * SKB;
#pragma unroll
    for (int i = 0; i < 2; ++i) {
        int idx = tid + i * 256;
        int r = idx >> 3, c = idx & 7;
        cp16(kd + (u32)(r * 144 + c * 16), kg + (size_t)(j0 + r) * 64 + c * 8);
    }
    u32 vb = sb + SV + (u32)buf * SVB;
#pragma unroll
    for (int i = 0; i < 8; ++i) {
        int idx = tid + i * 256;
        int r = idx >> 3, c = idx & 7;           // r = channel 0..255
        u32 doff = (u32)(r * 144 + c * 16);
        size_t soff = (size_t)r * HWDIM + j0 + c * 8;
        cp16(vb + doff, vh + soff);
        cp16(vb + SVLO + doff, vl + soff);
    }
}

__global__ __launch_bounds__(256, 1) void attn_kernel(
    const float* __restrict__ inp,
    const float* __restrict__ gamma_p,
    float* __restrict__ out)
{
    extern __shared__ char smem_raw[];
    const u32 sb = saddr(smem_raw);
    const int tid = threadIdx.x;
    const int lane = tid & 31;
    const int warp = tid >> 5;
    const int b = blockIdx.y;
    const int n0 = blockIdx.x * 64;
    const int q0 = (warp >> 1) * 16;
    const int c0 = (warp & 1) * 128;

    const __nv_bfloat16* qg = g_qhl + ((size_t)b * HWDIM + n0) * 64;
    const __nv_bfloat16* kg = g_khl + (size_t)b * HWDIM * 64;
    const __nv_bfloat16* vh = g_vh + (size_t)b * CD * HWDIM;
    const __nv_bfloat16* vl = g_vl + (size_t)b * CD * HWDIM;

    // Q tile + KV tile 0
#pragma unroll
    for (int i = 0; i < 2; ++i) {
        int idx = tid + i * 256;
        int r = idx >> 3, c = idx & 7;
        cp16(sb + SQ + (u32)(r * 144 + c * 16), qg + (size_t)r * 64 + c * 8);
    }
    load_kv_tile(sb, 0, 0, tid, kg, vh, vl);
    cp_commit();
    cp_wait0();
    __syncthreads();

    // Q fragments (held all kernel): Qh 2 ksteps, Ql 2 ksteps
    u32 qh[2][4], ql[2][4];
    {
        u32 base = sb + SQ + (u32)((q0 + (lane & 15)) * 144 + (lane >> 4) * 16);
        LDSM4(qh[0], base);
        LDSM4(qh[1], base + 32);
        LDSM4(ql[0], base + 64);
        LDSM4(ql[1], base + 96);
    }

    float o[16][4];
#pragma unroll
    for (int i = 0; i < 16; ++i) { o[i][0] = 0.f; o[i][1] = 0.f; o[i][2] = 0.f; o[i][3] = 0.f; }
    float lr0 = 0.f, lr1 = 0.f;

    for (int t = 0; t < NTILE; ++t) {
        const int buf = t & 1;
        if (t) cp_wait0();
        __syncthreads();                     // KV(t) visible; all warps done with buf^1
        if (t + 1 < NTILE) { load_kv_tile(sb, buf ^ 1, (t + 1) * 64, tid, kg, vh, vl); cp_commit(); }

        // ---- MMA1: S[16x64] = Qh·Kh + Qh·Kl + Ql·Kh ----
        float st[8][4];
        const u32 kbase = sb + SK + (u32)buf * SKB + (u32)((lane & 7) * 144 + (lane >> 3) * 16);
#pragma unroll
        for (int nt = 0; nt < 8; ++nt) {
            u32 bh[4], bl[4];
            LDSM4(bh, kbase + (u32)(nt * 1152));
            LDSM4(bl, kbase + (u32)(nt * 1152) + 64);
            st[nt][0] = 0.f; st[nt][1] = 0.f; st[nt][2] = 0.f; st[nt][3] = 0.f;
            MMA(st[nt], qh[0], bh[0], bh[1]);
            MMA(st[nt], qh[1], bh[2], bh[3]);
            MMA(st[nt], qh[0], bl[0], bl[1]);
            MMA(st[nt], qh[1], bl[2], bl[3]);
            MMA(st[nt], ql[0], bh[0], bh[1]);
            MMA(st[nt], ql[1], bh[2], bh[3]);
        }

        // ---- softmax (no max-sub) + pack P into A-fragments (hi/lo) ----
        u32 ph[4][4], pl[4][4];
#pragma unroll
        for (int nt = 0; nt < 8; ++nt) {
            float p0 = __expf(st[nt][0]);
            float p1 = __expf(st[nt][1]);
            float p2 = __expf(st[nt][2]);
            float p3 = __expf(st[nt][3]);
            lr0 += p0 + p1;
            lr1 += p2 + p3;
            u32 h0 = bf2(p0, p1), h1 = bf2(p2, p3);
            u32 L0 = bf2(p0 - lo16f(h0), p1 - hi16f(h0));
            u32 L1 = bf2(p2 - lo16f(h1), p3 - hi16f(h1));
            int ks = nt >> 1, hf = (nt & 1) * 2;
            ph[ks][hf] = h0; ph[ks][hf + 1] = h1;
            pl[ks][hf] = L0; pl[ks][hf + 1] = L1;
        }

        // ---- MMA2: O += Ph·Vh + Pl·Vh + Ph·Vl ----
        const u32 vbb = sb + SV + (u32)buf * SVB + (u32)((c0 + (lane & 7)) * 144 + (lane >> 3) * 16);
#pragma unroll
        for (int nt = 0; nt < 16; ++nt) {
            u32 vh0[4], vh1[4], vl0[4], vl1[4];
            u32 rb = vbb + (u32)(nt * 1152);
            LDSM4(vh0, rb);
            LDSM4(vh1, rb + 64);
            LDSM4(vl0, rb + SVLO);
            LDSM4(vl1, rb + SVLO + 64);
            MMA(o[nt], ph[0], vh0[0], vh0[1]);
            MMA(o[nt], ph[1], vh0[2], vh0[3]);
            MMA(o[nt], ph[2], vh1[0], vh1[1]);
            MMA(o[nt], ph[3], vh1[2], vh1[3]);
            MMA(o[nt], pl[0], vh0[0], vh0[1]);
            MMA(o[nt], pl[1], vh0[2], vh0[3]);
            MMA(o[nt], pl[2], vh1[0], vh1[1]);
            MMA(o[nt], pl[3], vh1[2], vh1[3]);
            MMA(o[nt], ph[0], vl0[0], vl0[1]);
            MMA(o[nt], ph[1], vl0[2], vl0[3]);
            MMA(o[nt], ph[2], vl1[0], vl1[1]);
            MMA(o[nt], ph[3], vl1[2], vl1[3]);
        }
    }

    // ---- epilogue ----
    lr0 += __shfl_xor_sync(0xffffffffu, lr0, 1);
    lr0 += __shfl_xor_sync(0xffffffffu, lr0, 2);
    lr1 += __shfl_xor_sync(0xffffffffu, lr1, 1);
    lr1 += __shfl_xor_sync(0xffffffffu, lr1, 2);
    float* ls = (float*)(smem_raw + LSOFF);
    if ((warp & 1) == 0 && (lane & 3) == 0) {
        ls[q0 + (lane >> 2)]     = lr0;
        ls[q0 + 8 + (lane >> 2)] = lr1;
    }
    __syncthreads();                       // ls ready; V buffers dead -> reuse as Osm

    float* Os = (float*)smem_raw;          // [256 c][68] f32
    if (tid < 64) ls[tid] = gamma_p[0] / ls[tid];
#pragma unroll
    for (int nt = 0; nt < 16; ++nt) {
        int cc = c0 + 8 * nt + 2 * (lane & 3);
        int qq = q0 + (lane >> 2);
        Os[cc * 68 + qq]            = o[nt][0];
        Os[(cc + 1) * 68 + qq]      = o[nt][1];
        Os[cc * 68 + qq + 8]        = o[nt][2];
        Os[(cc + 1) * 68 + qq + 8]  = o[nt][3];
    }
    __syncthreads();

    const float* ib = inp + (size_t)b * CD * HWDIM + n0;
    float* ob = out + (size_t)b * CD * HWDIM + n0;
#pragma unroll 4
    for (int it = 0; it < 64; ++it) {
        int idx = tid + it * 256;
        int c = idx >> 6, q = idx & 63;
        ob[(size_t)c * HWDIM + q] = Os[c * 68 + q] * ls[q] + ib[(size_t)c * HWDIM + q];
    }
}

// =====================================================================
extern "C" void kernel_launch(void* const* d_in, const int* in_sizes, int n_in,
                              void* d_out, int out_size)
{
    (void)in_sizes; (void)n_in; (void)out_size;
    const float* input    = (const float*)d_in[0];
    const float* original = (const float*)d_in[1];
    const float* wq    = (const float*)d_in[2];
    const float* bq    = (const float*)d_in[3];
    const float* wk    = (const float*)d_in[4];
    const float* bk    = (const float*)d_in[5];
    const float* wv    = (const float*)d_in[6];
    const float* bv    = (const float*)d_in[7];
    const float* gamma = (const float*)d_in[8];
    float* out = (float*)d_out;

    cudaFuncSetAttribute(attn_kernel, cudaFuncAttributeMaxDynamicSharedMemorySize, ATTN_SMEM);

    qk_proj_kernel<<<dim3(HWDIM / 64, NB), 256>>>(input, wq, bq, wk, bk);
    v_proj_kernel<<<dim3(HWDIM / 64, CD / 64, NB), 256>>>(original, wv, bv);
    attn_kernel<<<dim3(HWDIM / 64, NB), 256, ATTN_SMEM>>>(input, gamma, out);
}

// round 7
// speedup vs baseline: 3.2608x; 1.3554x over previous
#include <cuda_runtime.h>
#include <cuda_bf16.h>
#include <cstdint>

typedef unsigned long long u64;
typedef unsigned int       u32;

#define HWDIM 4096
#define CD    256
#define NB    4
#define NTILE 64

// ---------------- scratch (no allocations allowed) ----------------
__device__ __nv_bfloat16 g_qhl[(size_t)NB * HWDIM * 64];   // [b][n][Qh(32)|Ql(32)]
__device__ __nv_bfloat16 g_khl[(size_t)NB * HWDIM * 64];   // [b][n][Kh|Kl]
__device__ __nv_bfloat16 g_vh[(size_t)NB * CD * HWDIM];    // [b][c][n]

// ---------------- helpers ----------------
__device__ __forceinline__ u32 saddr(const void* p) { return (u32)__cvta_generic_to_shared(p); }
__device__ __forceinline__ void cp16(u32 dst, const void* src) {
    asm volatile("cp.async.cg.shared.global [%0], [%1], 16;" :: "r"(dst), "l"(src));
}
__device__ __forceinline__ void cp_commit() { asm volatile("cp.async.commit_group;" ::: "memory"); }
__device__ __forceinline__ void cp_wait0()  { asm volatile("cp.async.wait_group 0;" ::: "memory"); }

__device__ __forceinline__ u32 bf2(float lo, float hi) {
    u32 r; asm("cvt.rn.bf16x2.f32 %0, %1, %2;" : "=r"(r) : "f"(hi), "f"(lo)); return r;
}
__device__ __forceinline__ u64 pk64(u32 lo, u32 hi) {
    u64 r; asm("mov.b64 %0, {%1, %2};" : "=l"(r) : "r"(lo), "r"(hi)); return r;
}
__device__ __forceinline__ float lo16f(u32 h) { return __uint_as_float(h << 16); }
__device__ __forceinline__ float hi16f(u32 h) { return __uint_as_float(h & 0xFFFF0000u); }
__device__ __forceinline__ float f2lo(u64 v) { return __uint_as_float((u32)v); }
__device__ __forceinline__ float f2hi(u64 v) { return __uint_as_float((u32)(v >> 32)); }
__device__ __forceinline__ u64 ffma2(u64 a, u64 b, u64 c) {
    u64 d; asm("fma.rn.f32x2 %0, %1, %2, %3;" : "=l"(d) : "l"(a), "l"(b), "l"(c)); return d;
}
__device__ __forceinline__ u64 pack2(float lo, float hi) {
    u64 d; asm("mov.b64 %0, {%1, %2};" : "=l"(d) : "f"(lo), "f"(hi)); return d;
}

#define LDSM4(r, a) \
    asm volatile("ldmatrix.sync.aligned.m8n8.x4.shared.b16 {%0,%1,%2,%3}, [%4];" \
        : "=r"((r)[0]), "=r"((r)[1]), "=r"((r)[2]), "=r"((r)[3]) : "r"(a))

#define MMA(d, a, b0_, b1_) \
    asm volatile("mma.sync.aligned.m16n8k16.row.col.f32.bf16.bf16.f32 " \
        "{%0,%1,%2,%3}, {%4,%5,%6,%7}, {%8,%9}, {%0,%1,%2,%3};" \
        : "+f"((d)[0]), "+f"((d)[1]), "+f"((d)[2]), "+f"((d)[3]) \
        : "r"((a)[0]), "r"((a)[1]), "r"((a)[2]), "r"((a)[3]), "r"(b0_), "r"(b1_))

// =====================================================================
// QK projection (fp32 FFMA2) -> bf16 hi/lo splits [b][n][Qh|Ql]/[Kh|Kl]
// =====================================================================
__global__ __launch_bounds__(256) void qk_proj_kernel(
    const float* __restrict__ x,
    const float* __restrict__ wq, const float* __restrict__ bq,
    const float* __restrict__ wk, const float* __restrict__ bk)
{
    __shared__ float xs[64][65];
    __shared__ float ws[64][66];
    const int tid = threadIdx.x;
    const int b = blockIdx.y;
    const int n0 = blockIdx.x * 64;
    const int tx = tid & 15, ty = tid >> 4;

    u64 acc[4][2];
#pragma unroll
    for (int i = 0; i < 4; ++i) { acc[i][0] = 0ull; acc[i][1] = 0ull; }

    const float* xb = x + (size_t)b * CD * HWDIM;

    for (int c0 = 0; c0 < CD; c0 += 64) {
        __syncthreads();
#pragma unroll
        for (int it = 0; it < 16; ++it) {
            int idx = tid + it * 256;
            int cc = idx >> 6, nn = idx & 63;
            xs[cc][nn] = xb[(size_t)(c0 + cc) * HWDIM + n0 + nn];
        }
#pragma unroll
        for (int it = 0; it < 16; ++it) {
            int idx = tid + it * 256;
            int o = idx >> 6, cc = idx & 63;
            ws[cc][o] = (o < 32) ? wq[o * CD + c0 + cc] : wk[(o - 32) * CD + c0 + cc];
        }
        __syncthreads();
#pragma unroll 8
        for (int kk = 0; kk < 64; ++kk) {
            u64 a0 = *(const u64*)&ws[kk][ty * 4];
            u64 a1 = *(const u64*)&ws[kk][ty * 4 + 2];
#pragma unroll
            for (int i = 0; i < 4; ++i) {
                float bv2 = xs[kk][tx * 4 + i];
                u64 bd = pack2(bv2, bv2);
                acc[i][0] = ffma2(a0, bd, acc[i][0]);
                acc[i][1] = ffma2(a1, bd, acc[i][1]);
            }
        }
    }
    const int og = ty * 4;
    float bb0, bb1, bb2, bb3;
    if (ty < 8) { bb0 = bq[og]; bb1 = bq[og + 1]; bb2 = bq[og + 2]; bb3 = bq[og + 3]; }
    else        { bb0 = bk[og - 32]; bb1 = bk[og - 31]; bb2 = bk[og - 30]; bb3 = bk[og - 29]; }
    __nv_bfloat16* arr = (ty < 8) ? g_qhl : g_khl;
    const int ol = (ty < 8) ? og : og - 32;
#pragma unroll
    for (int i = 0; i < 4; ++i) {
        int n = n0 + tx * 4 + i;
        float f0 = f2lo(acc[i][0]) + bb0;
        float f1 = f2hi(acc[i][0]) + bb1;
        float f2 = f2lo(acc[i][1]) + bb2;
        float f3 = f2hi(acc[i][1]) + bb3;
        u32 h01 = bf2(f0, f1), h23 = bf2(f2, f3);
        u32 l01 = bf2(f0 - lo16f(h01), f1 - hi16f(h01));
        u32 l23 = bf2(f2 - lo16f(h23), f3 - hi16f(h23));
        __nv_bfloat16* base = arr + ((size_t)b * HWDIM + n) * 64 + ol;
        *(u64*)base        = pk64(h01, h23);
        *(u64*)(base + 32) = pk64(l01, l23);
    }
}

// =====================================================================
// V projection -> g_vh [b][c][n] bf16 (hi only; V-comp term dropped).
// =====================================================================
__global__ __launch_bounds__(256) void v_proj_kernel(
    const float* __restrict__ orig,
    const float* __restrict__ wv, const float* __restrict__ bv)
{
    __shared__ float xs[64][65];
    __shared__ float ws[64][66];
    const int tid = threadIdx.x;
    const int b = blockIdx.z;
    const int obase = blockIdx.y * 64;
    const int n0 = blockIdx.x * 64;
    const int tx = tid & 15, ty = tid >> 4;

    u64 acc[4][2];
#pragma unroll
    for (int i = 0; i < 4; ++i) { acc[i][0] = 0ull; acc[i][1] = 0ull; }

    const float* xb = orig + (size_t)b * CD * HWDIM;

    for (int c0 = 0; c0 < CD; c0 += 64) {
        __syncthreads();
#pragma unroll
        for (int it = 0; it < 16; ++it) {
            int idx = tid + it * 256;
            int cc = idx >> 6, nn = idx & 63;
            xs[cc][nn] = xb[(size_t)(c0 + cc) * HWDIM + n0 + nn];
        }
#pragma unroll
        for (int it = 0; it < 16; ++it) {
            int idx = tid + it * 256;
            int o = idx >> 6, cc = idx & 63;
            ws[cc][o] = wv[(size_t)(obase + o) * CD + c0 + cc];
        }
        __syncthreads();
#pragma unroll 8
        for (int kk = 0; kk < 64; ++kk) {
            u64 a0 = *(const u64*)&ws[kk][ty * 4];
            u64 a1 = *(const u64*)&ws[kk][ty * 4 + 2];
#pragma unroll
            for (int i = 0; i < 4; ++i) {
                float bv2 = xs[kk][tx * 4 + i];
                u64 bd = pack2(bv2, bv2);
                acc[i][0] = ffma2(a0, bd, acc[i][0]);
                acc[i][1] = ffma2(a1, bd, acc[i][1]);
            }
        }
    }
#pragma unroll
    for (int ol = 0; ol < 4; ++ol) {
        int c = obase + ty * 4 + ol;
        float bb = bv[c];
        float f[4];
#pragma unroll
        for (int i = 0; i < 4; ++i) {
            u64 a = acc[i][ol >> 1];
            f[i] = ((ol & 1) ? f2hi(a) : f2lo(a)) + bb;
        }
        u32 h01 = bf2(f[0], f[1]), h23 = bf2(f[2], f[3]);
        size_t off = ((size_t)b * CD + c) * HWDIM + n0 + tx * 4;
        *(u64*)(g_vh + off) = pk64(h01, h23);
    }
}

// =====================================================================
// Flash attention via mma.sync m16n8k16 bf16.
// S = Qh·Kh + Qh·Kl + Ql·Kh ; O += Ph·Vh + Pl·Vh (V-comp dropped).
// 256 threads (8 warps); warp = 16 q x 128 c; CTA = 64 q; grid (64, 4).
// 2 CTAs/SM (99.25 KB smem each) -> one wave, cross-CTA stall overlap.
// =====================================================================
#define SQ   0u
#define SK   9216u          // 2 bufs x 64 x 144
#define SKB  9216u
#define SV   27648u         // 2 bufs x 256 x 144 (hi only)
#define SVB  36864u
#define LSOFF 101376u
#define ATTN_SMEM 101632

__device__ __forceinline__ void load_kv_tile(u32 sb, int buf, int j0, int tid,
    const __nv_bfloat16* kg, const __nv_bfloat16* vh)
{
    u32 kd = sb + SK + (u32)buf * SKB;
#pragma unroll
    for (int i = 0; i < 2; ++i) {
        int idx = tid + i * 256;
        int r = idx >> 3, c = idx & 7;
        cp16(kd + (u32)(r * 144 + c * 16), kg + (size_t)(j0 + r) * 64 + c * 8);
    }
    u32 vb = sb + SV + (u32)buf * SVB;
#pragma unroll
    for (int i = 0; i < 8; ++i) {
        int idx = tid + i * 256;
        int r = idx >> 3, c = idx & 7;           // r = channel 0..255
        cp16(vb + (u32)(r * 144 + c * 16), vh + (size_t)r * HWDIM + j0 + c * 8);
    }
}

__global__ __launch_bounds__(256, 2) void attn_kernel(
    const float* __restrict__ inp,
    const float* __restrict__ gamma_p,
    float* __restrict__ out)
{
    extern __shared__ char smem_raw[];
    const u32 sb = saddr(smem_raw);
    const int tid = threadIdx.x;
    const int lane = tid & 31;
    const int warp = tid >> 5;
    const int b = blockIdx.y;
    const int n0 = blockIdx.x * 64;
    const int q0 = (warp >> 1) * 16;
    const int c0 = (warp & 1) * 128;

    const __nv_bfloat16* qg = g_qhl + ((size_t)b * HWDIM + n0) * 64;
    const __nv_bfloat16* kg = g_khl + (size_t)b * HWDIM * 64;
    const __nv_bfloat16* vh = g_vh + (size_t)b * CD * HWDIM;

    // Q tile + KV tile 0
#pragma unroll
    for (int i = 0; i < 2; ++i) {
        int idx = tid + i * 256;
        int r = idx >> 3, c = idx & 7;
        cp16(sb + SQ + (u32)(r * 144 + c * 16), qg + (size_t)r * 64 + c * 8);
    }
    load_kv_tile(sb, 0, 0, tid, kg, vh);
    cp_commit();
    cp_wait0();
    __syncthreads();

    // Q fragments (held all kernel): Qh 2 ksteps, Ql 2 ksteps
    u32 qh[2][4], ql[2][4];
    {
        u32 base = sb + SQ + (u32)((q0 + (lane & 15)) * 144 + (lane >> 4) * 16);
        LDSM4(qh[0], base);
        LDSM4(qh[1], base + 32);
        LDSM4(ql[0], base + 64);
        LDSM4(ql[1], base + 96);
    }

    float o[16][4];
#pragma unroll
    for (int i = 0; i < 16; ++i) { o[i][0] = 0.f; o[i][1] = 0.f; o[i][2] = 0.f; o[i][3] = 0.f; }
    float lr0 = 0.f, lr1 = 0.f;

    for (int t = 0; t < NTILE; ++t) {
        const int buf = t & 1;
        if (t) cp_wait0();
        __syncthreads();                     // KV(t) visible; all warps done with buf^1
        if (t + 1 < NTILE) { load_kv_tile(sb, buf ^ 1, (t + 1) * 64, tid, kg, vh); cp_commit(); }

        // ---- MMA1 + softmax fused per n-tile: S = Qh·Kh + Qh·Kl + Ql·Kh ----
        u32 ph[4][4], pl[4][4];
        const u32 kbase = sb + SK + (u32)buf * SKB + (u32)((lane & 7) * 144 + (lane >> 3) * 16);
#pragma unroll
        for (int nt = 0; nt < 8; ++nt) {
            u32 bh[4], bl[4];
            LDSM4(bh, kbase + (u32)(nt * 1152));
            LDSM4(bl, kbase + (u32)(nt * 1152) + 64);
            float st[4];
            st[0] = 0.f; st[1] = 0.f; st[2] = 0.f; st[3] = 0.f;
            MMA(st, qh[0], bh[0], bh[1]);
            MMA(st, qh[1], bh[2], bh[3]);
            MMA(st, qh[0], bl[0], bl[1]);
            MMA(st, qh[1], bl[2], bl[3]);
            MMA(st, ql[0], bh[0], bh[1]);
            MMA(st, ql[1], bh[2], bh[3]);
            float p0 = __expf(st[0]);
            float p1 = __expf(st[1]);
            float p2 = __expf(st[2]);
            float p3 = __expf(st[3]);
            lr0 += p0 + p1;
            lr1 += p2 + p3;
            u32 h0 = bf2(p0, p1), h1 = bf2(p2, p3);
            u32 L0 = bf2(p0 - lo16f(h0), p1 - hi16f(h0));
            u32 L1 = bf2(p2 - lo16f(h1), p3 - hi16f(h1));
            int ks = nt >> 1, hf = (nt & 1) * 2;
            ph[ks][hf] = h0; ph[ks][hf + 1] = h1;
            pl[ks][hf] = L0; pl[ks][hf + 1] = L1;
        }

        // ---- MMA2: O += Ph·Vh + Pl·Vh ----
        const u32 vbb = sb + SV + (u32)buf * SVB + (u32)((c0 + (lane & 7)) * 144 + (lane >> 3) * 16);
#pragma unroll
        for (int nt = 0; nt < 16; ++nt) {
            u32 vh0[4], vh1[4];
            u32 rb = vbb + (u32)(nt * 1152);
            LDSM4(vh0, rb);
            LDSM4(vh1, rb + 64);
            MMA(o[nt], ph[0], vh0[0], vh0[1]);
            MMA(o[nt], ph[1], vh0[2], vh0[3]);
            MMA(o[nt], ph[2], vh1[0], vh1[1]);
            MMA(o[nt], ph[3], vh1[2], vh1[3]);
            MMA(o[nt], pl[0], vh0[0], vh0[1]);
            MMA(o[nt], pl[1], vh0[2], vh0[3]);
            MMA(o[nt], pl[2], vh1[0], vh1[1]);
            MMA(o[nt], pl[3], vh1[2], vh1[3]);
        }
    }

    // ---- epilogue ----
    lr0 += __shfl_xor_sync(0xffffffffu, lr0, 1);
    lr0 += __shfl_xor_sync(0xffffffffu, lr0, 2);
    lr1 += __shfl_xor_sync(0xffffffffu, lr1, 1);
    lr1 += __shfl_xor_sync(0xffffffffu, lr1, 2);
    float* ls = (float*)(smem_raw + LSOFF);
    if ((warp & 1) == 0 && (lane & 3) == 0) {
        ls[q0 + (lane >> 2)]     = lr0;
        ls[q0 + 8 + (lane >> 2)] = lr1;
    }
    __syncthreads();                       // ls ready; K/V buffers dead -> reuse as Os

    float* Os = (float*)smem_raw;          // [256 c][68] f32
    if (tid < 64) ls[tid] = gamma_p[0] / ls[tid];
#pragma unroll
    for (int nt = 0; nt < 16; ++nt) {
        int cc = c0 + 8 * nt + 2 * (lane & 3);
        int qq = q0 + (lane >> 2);
        Os[cc * 68 + qq]            = o[nt][0];
        Os[(cc + 1) * 68 + qq]      = o[nt][1];
        Os[cc * 68 + qq + 8]        = o[nt][2];
        Os[(cc + 1) * 68 + qq + 8]  = o[nt][3];
    }
    __syncthreads();

    const float* ib = inp + (size_t)b * CD * HWDIM + n0;
    float* ob = out + (size_t)b * CD * HWDIM + n0;
#pragma unroll 4
    for (int it = 0; it < 64; ++it) {
        int idx = tid + it * 256;
        int c = idx >> 6, q = idx & 63;
        ob[(size_t)c * HWDIM + q] = Os[c * 68 + q] * ls[q] + ib[(size_t)c * HWDIM + q];
    }
}

// =====================================================================
extern "C" void kernel_launch(void* const* d_in, const int* in_sizes, int n_in,
                              void* d_out, int out_size)
{
    (void)in_sizes; (void)n_in; (void)out_size;
    const float* input    = (const float*)d_in[0];
    const float* original = (const float*)d_in[1];
    const float* wq    = (const float*)d_in[2];
    const float* bq    = (const float*)d_in[3];
    const float* wk    = (const float*)d_in[4];
    const float* bk    = (const float*)d_in[5];
    const float* wv    = (const float*)d_in[6];
    const float* bv    = (const float*)d_in[7];
    const float* gamma = (const float*)d_in[8];
    float* out = (float*)d_out;

    cudaFuncSetAttribute(attn_kernel, cudaFuncAttributeMaxDynamicSharedMemorySize, ATTN_SMEM);

    qk_proj_kernel<<<dim3(HWDIM / 64, NB), 256>>>(input, wq, bq, wk, bk);
    v_proj_kernel<<<dim3(HWDIM / 64, CD / 64, NB), 256>>>(original, wv, bv);
    attn_kernel<<<dim3(HWDIM / 64, NB), 256, ATTN_SMEM>>>(input, gamma, out);
}

// round 11
// speedup vs baseline: 3.5961x; 1.1028x over previous
#include <cuda_runtime.h>
#include <cuda_bf16.h>
#include <cstdint>

typedef unsigned long long u64;
typedef unsigned int       u32;

#define HWDIM 4096
#define CD    256
#define NB    4
#define NTILE 64
#define LOG2E 1.4426950408889634f

// ---------------- scratch (no allocations allowed) ----------------
__device__ __nv_bfloat16 g_qhl[(size_t)NB * HWDIM * 64];   // [b][n][Qh(32)|Ql(32)] (Q pre-scaled by log2e)
__device__ __nv_bfloat16 g_khl[(size_t)NB * HWDIM * 64];   // [b][n][Kh|Kl]
__device__ __nv_bfloat16 g_vh[(size_t)NB * CD * HWDIM];    // [b][c][n]
__device__ __nv_bfloat16 g_oh[(size_t)NB * HWDIM * CD];    // [b][n][c]  orig hi
__device__ __nv_bfloat16 g_ol[(size_t)NB * HWDIM * CD];    // [b][n][c]  orig lo
__device__ __nv_bfloat16 g_wvh[CD * CD];                   // [c][k]
__device__ __nv_bfloat16 g_wvl[CD * CD];

// ---------------- helpers ----------------
__device__ __forceinline__ u32 saddr(const void* p) { return (u32)__cvta_generic_to_shared(p); }
__device__ __forceinline__ void cp16(u32 dst, const void* src) {
    asm volatile("cp.async.cg.shared.global [%0], [%1], 16;" :: "r"(dst), "l"(src));
}
__device__ __forceinline__ void cp_commit() { asm volatile("cp.async.commit_group;" ::: "memory"); }
__device__ __forceinline__ void cp_wait0()  { asm volatile("cp.async.wait_group 0;" ::: "memory"); }

__device__ __forceinline__ u32 bf2(float lo, float hi) {
    u32 r; asm("cvt.rn.bf16x2.f32 %0, %1, %2;" : "=r"(r) : "f"(hi), "f"(lo)); return r;
}
__device__ __forceinline__ u64 pk64(u32 lo, u32 hi) {
    u64 r; asm("mov.b64 %0, {%1, %2};" : "=l"(r) : "r"(lo), "r"(hi)); return r;
}
__device__ __forceinline__ float lo16f(u32 h) { return __uint_as_float(h << 16); }
__device__ __forceinline__ float hi16f(u32 h) { return __uint_as_float(h & 0xFFFF0000u); }
__device__ __forceinline__ float f2lo(u64 v) { return __uint_as_float((u32)v); }
__device__ __forceinline__ float f2hi(u64 v) { return __uint_as_float((u32)(v >> 32)); }
__device__ __forceinline__ u64 ffma2(u64 a, u64 b, u64 c) {
    u64 d; asm("fma.rn.f32x2 %0, %1, %2, %3;" : "=l"(d) : "l"(a), "l"(b), "l"(c)); return d;
}
__device__ __forceinline__ u64 pack2(float lo, float hi) {
    u64 d; asm("mov.b64 %0, {%1, %2};" : "=l"(d) : "f"(lo), "f"(hi)); return d;
}
__device__ __forceinline__ float ex2f(float x) {
    float r; asm("ex2.approx.f32 %0, %1;" : "=f"(r) : "f"(x)); return r;
}

#define LDSM4(r, a) \
    asm volatile("ldmatrix.sync.aligned.m8n8.x4.shared.b16 {%0,%1,%2,%3}, [%4];" \
        : "=r"((r)[0]), "=r"((r)[1]), "=r"((r)[2]), "=r"((r)[3]) : "r"(a))

#define MMA(d, a, b0_, b1_) \
    asm volatile("mma.sync.aligned.m16n8k16.row.col.f32.bf16.bf16.f32 " \
        "{%0,%1,%2,%3}, {%4,%5,%6,%7}, {%8,%9}, {%0,%1,%2,%3};" \
        : "+f"((d)[0]), "+f"((d)[1]), "+f"((d)[2]), "+f"((d)[3]) \
        : "r"((a)[0]), "r"((a)[1]), "r"((a)[2]), "r"((a)[3]), "r"(b0_), "r"(b1_))

// =====================================================================
// Split+transpose: orig [b][c][n] fp32 -> g_oh/g_ol [b][n][c] bf16
// =====================================================================
__global__ __launch_bounds__(256) void split_orig_kernel(const float* __restrict__ orig)
{
    __shared__ float xs[64][65];
    const int tid = threadIdx.x;
    const int b = blockIdx.z;
    const int c0 = blockIdx.y * 64;
    const int n0 = blockIdx.x * 64;
    const float* ob = orig + ((size_t)b * CD + c0) * HWDIM + n0;
#pragma unroll
    for (int it = 0; it < 16; ++it) {
        int idx = tid + it * 256;
        int cc = idx >> 6, nn = idx & 63;
        xs[cc][nn] = ob[(size_t)cc * HWDIM + nn];
    }
    __syncthreads();
    // 64 n x 16 c-quads = 1024 work items -> 4 iterations (NOT 16: was the R8 OOB bug)
#pragma unroll
    for (int it = 0; it < 4; ++it) {
        int idx = tid + it * 256;
        int n = idx >> 4, c4 = (idx & 15) * 4;
        float y0 = xs[c4][n], y1 = xs[c4 + 1][n], y2 = xs[c4 + 2][n], y3 = xs[c4 + 3][n];
        u32 h01 = bf2(y0, y1), h23 = bf2(y2, y3);
        u32 l01 = bf2(y0 - lo16f(h01), y1 - hi16f(h01));
        u32 l23 = bf2(y2 - lo16f(h23), y3 - hi16f(h23));
        size_t off = ((size_t)b * HWDIM + n0 + n) * CD + c0 + c4;
        *(u64*)(g_oh + off) = pk64(h01, h23);
        *(u64*)(g_ol + off) = pk64(l01, l23);
    }
}

// wv [c][k] fp32 -> g_wvh/g_wvl bf16 (same layout)
__global__ __launch_bounds__(256) void split_wv_kernel(const float* __restrict__ wv)
{
    int i = (blockIdx.x * 256 + threadIdx.x) * 4;
    float y0 = wv[i], y1 = wv[i + 1], y2 = wv[i + 2], y3 = wv[i + 3];
    u32 h01 = bf2(y0, y1), h23 = bf2(y2, y3);
    u32 l01 = bf2(y0 - lo16f(h01), y1 - hi16f(h01));
    u32 l23 = bf2(y2 - lo16f(h23), y3 - hi16f(h23));
    *(u64*)(g_wvh + i) = pk64(h01, h23);
    *(u64*)(g_wvl + i) = pk64(l01, l23);
}

// =====================================================================
// QK projection (fp32 FFMA2) -> bf16 hi/lo splits; Q scaled by log2e.
// =====================================================================
__global__ __launch_bounds__(256) void qk_proj_kernel(
    const float* __restrict__ x,
    const float* __restrict__ wq, const float* __restrict__ bq,
    const float* __restrict__ wk, const float* __restrict__ bk)
{
    __shared__ float xs[64][65];
    __shared__ float ws[64][66];
    const int tid = threadIdx.x;
    const int b = blockIdx.y;
    const int n0 = blockIdx.x * 64;
    const int tx = tid & 15, ty = tid >> 4;

    u64 acc[4][2];
#pragma unroll
    for (int i = 0; i < 4; ++i) { acc[i][0] = 0ull; acc[i][1] = 0ull; }

    const float* xb = x + (size_t)b * CD * HWDIM;

    for (int c0 = 0; c0 < CD; c0 += 64) {
        __syncthreads();
#pragma unroll
        for (int it = 0; it < 16; ++it) {
            int idx = tid + it * 256;
            int cc = idx >> 6, nn = idx & 63;
            xs[cc][nn] = xb[(size_t)(c0 + cc) * HWDIM + n0 + nn];
        }
#pragma unroll
        for (int it = 0; it < 16; ++it) {
            int idx = tid + it * 256;
            int o = idx >> 6, cc = idx & 63;
            ws[cc][o] = (o < 32) ? wq[o * CD + c0 + cc] : wk[(o - 32) * CD + c0 + cc];
        }
        __syncthreads();
#pragma unroll 8
        for (int kk = 0; kk < 64; ++kk) {
            u64 a0 = *(const u64*)&ws[kk][ty * 4];
            u64 a1 = *(const u64*)&ws[kk][ty * 4 + 2];
#pragma unroll
            for (int i = 0; i < 4; ++i) {
                float bv2 = xs[kk][tx * 4 + i];
                u64 bd = pack2(bv2, bv2);
                acc[i][0] = ffma2(a0, bd, acc[i][0]);
                acc[i][1] = ffma2(a1, bd, acc[i][1]);
            }
        }
    }
    const int og = ty * 4;
    float bb0, bb1, bb2, bb3;
    if (ty < 8) { bb0 = bq[og]; bb1 = bq[og + 1]; bb2 = bq[og + 2]; bb3 = bq[og + 3]; }
    else        { bb0 = bk[og - 32]; bb1 = bk[og - 31]; bb2 = bk[og - 30]; bb3 = bk[og - 29]; }
    __nv_bfloat16* arr = (ty < 8) ? g_qhl : g_khl;
    const int ol = (ty < 8) ? og : og - 32;
    const float sc = (ty < 8) ? LOG2E : 1.0f;   // fold log2e into Q -> attn uses ex2
#pragma unroll
    for (int i = 0; i < 4; ++i) {
        int n = n0 + tx * 4 + i;
        float f0 = (f2lo(acc[i][0]) + bb0) * sc;
        float f1 = (f2hi(acc[i][0]) + bb1) * sc;
        float f2 = (f2lo(acc[i][1]) + bb2) * sc;
        float f3 = (f2hi(acc[i][1]) + bb3) * sc;
        u32 h01 = bf2(f0, f1), h23 = bf2(f2, f3);
        u32 l01 = bf2(f0 - lo16f(h01), f1 - hi16f(h01));
        u32 l23 = bf2(f2 - lo16f(h23), f3 - hi16f(h23));
        __nv_bfloat16* base = arr + ((size_t)b * HWDIM + n) * 64 + ol;
        *(u64*)base        = pk64(h01, h23);
        *(u64*)(base + 32) = pk64(l01, l23);
    }
}

// =====================================================================
// V projection via mma.sync bf16 (3-term): g_vh[b][c][n] = wv·orig + bv
// CTA: 64 c x 256 n, K=256 (4 k-steps of 64). 8 warps: 16c x 128n each.
// =====================================================================
#define VSWH 0u
#define VSWL 33792u
#define VSB  67584u
#define VSBB 73728u
#define VSXL 36864u
#define VPROJ_SMEM 215040

__global__ __launch_bounds__(256, 1) void v_proj_mma_kernel(const float* __restrict__ bv)
{
    extern __shared__ char smem_raw[];
    const u32 sb = saddr(smem_raw);
    const int tid = threadIdx.x;
    const int lane = tid & 31;
    const int warp = tid >> 5;
    const int b = blockIdx.z;
    const int ctile = blockIdx.y * 64;
    const int n0 = blockIdx.x * 256;
    const int rm = warp >> 1;            // c-row block (16 rows)
    const int nh = warp & 1;             // n half (128)

    const __nv_bfloat16* xh = g_oh + (size_t)b * HWDIM * CD;
    const __nv_bfloat16* xl = g_ol + (size_t)b * HWDIM * CD;

    // load A (w tiles, full K) : 64 rows x 512B, pitch 528
#pragma unroll
    for (int it = 0; it < 8; ++it) {
        int idx = tid + it * 256;
        int r = idx >> 5, ch = idx & 31;
        cp16(sb + VSWH + (u32)(r * 528 + ch * 16), g_wvh + (ctile + r) * CD + ch * 8);
        cp16(sb + VSWL + (u32)(r * 528 + ch * 16), g_wvl + (ctile + r) * CD + ch * 8);
    }
    // load B k-step 0
#pragma unroll
    for (int it = 0; it < 8; ++it) {
        int idx = tid + it * 256;
        int r = idx >> 3, ch = idx & 7;
        u32 doff = (u32)(r * 144 + ch * 16);
        size_t soff = (size_t)(n0 + r) * CD + ch * 8;
        cp16(sb + VSB + doff, xh + soff);
        cp16(sb + VSB + VSXL + doff, xl + soff);
    }
    cp_commit();

    float o[16][4];
#pragma unroll
    for (int i = 0; i < 16; ++i) { o[i][0] = 0.f; o[i][1] = 0.f; o[i][2] = 0.f; o[i][3] = 0.f; }

    for (int ks = 0; ks < 4; ++ks) {
        const int buf = ks & 1;
        cp_wait0();
        __syncthreads();
        if (ks < 3) {
#pragma unroll
            for (int it = 0; it < 8; ++it) {
                int idx = tid + it * 256;
                int r = idx >> 3, ch = idx & 7;
                u32 doff = (u32)((buf ^ 1) * VSBB + r * 144 + ch * 16);
                size_t soff = (size_t)(n0 + r) * CD + (ks + 1) * 64 + ch * 8;
                cp16(sb + VSB + doff, xh + soff);
                cp16(sb + VSB + VSXL + doff, xl + soff);
            }
            cp_commit();
        }

        u32 wh[4][4], wl[4][4];
        {
            u32 abase = sb + (u32)((rm * 16 + (lane & 15)) * 528 + ks * 128 + (lane >> 4) * 16);
#pragma unroll
            for (int j = 0; j < 4; ++j) {
                LDSM4(wh[j], abase + VSWH + (u32)(j * 32));
                LDSM4(wl[j], abase + VSWL + (u32)(j * 32));
            }
        }
        const u32 vbb = sb + VSB + (u32)buf * VSBB + (u32)((nh * 128 + (lane & 7)) * 144 + (lane >> 3) * 16);
#pragma unroll
        for (int nt = 0; nt < 16; ++nt) {
            u32 xh0[4], xh1[4], xl0[4], xl1[4];
            u32 rb = vbb + (u32)(nt * 1152);
            LDSM4(xh0, rb);
            LDSM4(xh1, rb + 64);
            LDSM4(xl0, rb + VSXL);
            LDSM4(xl1, rb + VSXL + 64);
            MMA(o[nt], wh[0], xh0[0], xh0[1]);
            MMA(o[nt], wh[1], xh0[2], xh0[3]);
            MMA(o[nt], wh[2], xh1[0], xh1[1]);
            MMA(o[nt], wh[3], xh1[2], xh1[3]);
            MMA(o[nt], wh[0], xl0[0], xl0[1]);
            MMA(o[nt], wh[1], xl0[2], xl0[3]);
            MMA(o[nt], wh[2], xl1[0], xl1[1]);
            MMA(o[nt], wh[3], xl1[2], xl1[3]);
            MMA(o[nt], wl[0], xh0[0], xh0[1]);
            MMA(o[nt], wl[1], xh0[2], xh0[3]);
            MMA(o[nt], wl[2], xh1[0], xh1[1]);
            MMA(o[nt], wl[3], xh1[2], xh1[3]);
        }
    }

    // epilogue: add bias, pack bf16, store [c][n]
    const int r0 = rm * 16 + (lane >> 2);
    const float b0 = bv[ctile + r0];
    const float b1 = bv[ctile + r0 + 8];
    __nv_bfloat16* v0 = g_vh + ((size_t)b * CD + ctile + r0) * HWDIM + n0 + nh * 128 + 2 * (lane & 3);
    __nv_bfloat16* v1 = v0 + (size_t)8 * HWDIM;
#pragma unroll
    for (int nt = 0; nt < 16; ++nt) {
        *(u32*)(v0 + nt * 8) = bf2(o[nt][0] + b0, o[nt][1] + b0);
        *(u32*)(v1 + nt * 8) = bf2(o[nt][2] + b1, o[nt][3] + b1);
    }
}

// =====================================================================
// Flash attention via mma.sync m16n8k16 bf16.
// S' = log2e*S (folded into Q); P = ex2(S'). O += Ph·Vh + Pl·Vh.
// 256 threads (8 warps); warp = 16 q x 128 c; CTA = 64 q; grid (64, 4).
// 2 CTAs/SM.
// =====================================================================
#define SQ   0u
#define SK   9216u
#define SKB  9216u
#define SV   27648u
#define SVB  36864u
#define LSOFF 101376u
#define ATTN_SMEM 101632

__device__ __forceinline__ void load_kv_tile(u32 sb, int buf, int j0, int tid,
    const __nv_bfloat16* kg, const __nv_bfloat16* vh)
{
    u32 kd = sb + SK + (u32)buf * SKB;
#pragma unroll
    for (int i = 0; i < 2; ++i) {
        int idx = tid + i * 256;
        int r = idx >> 3, c = idx & 7;
        cp16(kd + (u32)(r * 144 + c * 16), kg + (size_t)(j0 + r) * 64 + c * 8);
    }
    u32 vb = sb + SV + (u32)buf * SVB;
#pragma unroll
    for (int i = 0; i < 8; ++i) {
        int idx = tid + i * 256;
        int r = idx >> 3, c = idx & 7;
        cp16(vb + (u32)(r * 144 + c * 16), vh + (size_t)r * HWDIM + j0 + c * 8);
    }
}

__global__ __launch_bounds__(256, 2) void attn_kernel(
    const float* __restrict__ inp,
    const float* __restrict__ gamma_p,
    float* __restrict__ out)
{
    extern __shared__ char smem_raw[];
    const u32 sb = saddr(smem_raw);
    const int tid = threadIdx.x;
    const int lane = tid & 31;
    const int warp = tid >> 5;
    const int b = blockIdx.y;
    const int n0 = blockIdx.x * 64;
    const int q0 = (warp >> 1) * 16;
    const int c0 = (warp & 1) * 128;

    const __nv_bfloat16* qg = g_qhl + ((size_t)b * HWDIM + n0) * 64;
    const __nv_bfloat16* kg = g_khl + (size_t)b * HWDIM * 64;
    const __nv_bfloat16* vh = g_vh + (size_t)b * CD * HWDIM;

#pragma unroll
    for (int i = 0; i < 2; ++i) {
        int idx = tid + i * 256;
        int r = idx >> 3, c = idx & 7;
        cp16(sb + SQ + (u32)(r * 144 + c * 16), qg + (size_t)r * 64 + c * 8);
    }
    load_kv_tile(sb, 0, 0, tid, kg, vh);
    cp_commit();
    cp_wait0();
    __syncthreads();

    u32 qh[2][4], ql[2][4];
    {
        u32 base = sb + SQ + (u32)((q0 + (lane & 15)) * 144 + (lane >> 4) * 16);
        LDSM4(qh[0], base);
        LDSM4(qh[1], base + 32);
        LDSM4(ql[0], base + 64);
        LDSM4(ql[1], base + 96);
    }

    float o[16][4];
#pragma unroll
    for (int i = 0; i < 16; ++i) { o[i][0] = 0.f; o[i][1] = 0.f; o[i][2] = 0.f; o[i][3] = 0.f; }
    float lr0 = 0.f, lr1 = 0.f;

    for (int t = 0; t < NTILE; ++t) {
        const int buf = t & 1;
        if (t) cp_wait0();
        __syncthreads();
        if (t + 1 < NTILE) { load_kv_tile(sb, buf ^ 1, (t + 1) * 64, tid, kg, vh); cp_commit(); }

        // ---- MMA1 + softmax fused: S' = Qh·Kh + Qh·Kl + Ql·Kh (pre-scaled) ----
        u32 ph[4][4], pl[4][4];
        const u32 kbase = sb + SK + (u32)buf * SKB + (u32)((lane & 7) * 144 + (lane >> 3) * 16);
#pragma unroll
        for (int nt = 0; nt < 8; ++nt) {
            u32 bh[4], bl[4];
            LDSM4(bh, kbase + (u32)(nt * 1152));
            LDSM4(bl, kbase + (u32)(nt * 1152) + 64);
            float st[4];
            st[0] = 0.f; st[1] = 0.f; st[2] = 0.f; st[3] = 0.f;
            MMA(st, qh[0], bh[0], bh[1]);
            MMA(st, qh[1], bh[2], bh[3]);
            MMA(st, qh[0], bl[0], bl[1]);
            MMA(st, qh[1], bl[2], bl[3]);
            MMA(st, ql[0], bh[0], bh[1]);
            MMA(st, ql[1], bh[2], bh[3]);
            float p0 = ex2f(st[0]);
            float p1 = ex2f(st[1]);
            float p2 = ex2f(st[2]);
            float p3 = ex2f(st[3]);
            lr0 += p0 + p1;
            lr1 += p2 + p3;
            u32 h0 = bf2(p0, p1), h1 = bf2(p2, p3);
            u32 L0 = bf2(p0 - lo16f(h0), p1 - hi16f(h0));
            u32 L1 = bf2(p2 - lo16f(h1), p3 - hi16f(h1));
            int ks = nt >> 1, hf = (nt & 1) * 2;
            ph[ks][hf] = h0; ph[ks][hf + 1] = h1;
            pl[ks][hf] = L0; pl[ks][hf + 1] = L1;
        }

        // ---- MMA2: O += Ph·Vh + Pl·Vh ----
        const u32 vbb = sb + SV + (u32)buf * SVB + (u32)((c0 + (lane & 7)) * 144 + (lane >> 3) * 16);
#pragma unroll
        for (int nt = 0; nt < 16; ++nt) {
            u32 vh0[4], vh1[4];
            u32 rb = vbb + (u32)(nt * 1152);
            LDSM4(vh0, rb);
            LDSM4(vh1, rb + 64);
            MMA(o[nt], ph[0], vh0[0], vh0[1]);
            MMA(o[nt], ph[1], vh0[2], vh0[3]);
            MMA(o[nt], ph[2], vh1[0], vh1[1]);
            MMA(o[nt], ph[3], vh1[2], vh1[3]);
            MMA(o[nt], pl[0], vh0[0], vh0[1]);
            MMA(o[nt], pl[1], vh0[2], vh0[3]);
            MMA(o[nt], pl[2], vh1[0], vh1[1]);
            MMA(o[nt], pl[3], vh1[2], vh1[3]);
        }
    }

    // ---- epilogue ----
    lr0 += __shfl_xor_sync(0xffffffffu, lr0, 1);
    lr0 += __shfl_xor_sync(0xffffffffu, lr0, 2);
    lr1 += __shfl_xor_sync(0xffffffffu, lr1, 1);
    lr1 += __shfl_xor_sync(0xffffffffu, lr1, 2);
    float* ls = (float*)(smem_raw + LSOFF);
    if ((warp & 1) == 0 && (lane & 3) == 0) {
        ls[q0 + (lane >> 2)]     = lr0;
        ls[q0 + 8 + (lane >> 2)] = lr1;
    }
    __syncthreads();

    float* Os = (float*)smem_raw;
    if (tid < 64) ls[tid] = gamma_p[0] / ls[tid];
#pragma unroll
    for (int nt = 0; nt < 16; ++nt) {
        int cc = c0 + 8 * nt + 2 * (lane & 3);
        int qq = q0 + (lane >> 2);
        Os[cc * 68 + qq]            = o[nt][0];
        Os[(cc + 1) * 68 + qq]      = o[nt][1];
        Os[cc * 68 + qq + 8]        = o[nt][2];
        Os[(cc + 1) * 68 + qq + 8]  = o[nt][3];
    }
    __syncthreads();

    const float* ib = inp + (size_t)b * CD * HWDIM + n0;
    float* ob = out + (size_t)b * CD * HWDIM + n0;
#pragma unroll 4
    for (int it = 0; it < 64; ++it) {
        int idx = tid + it * 256;
        int c = idx >> 6, q = idx & 63;
        ob[(size_t)c * HWDIM + q] = Os[c * 68 + q] * ls[q] + ib[(size_t)c * HWDIM + q];
    }
}

// =====================================================================
extern "C" void kernel_launch(void* const* d_in, const int* in_sizes, int n_in,
                              void* d_out, int out_size)
{
    (void)in_sizes; (void)n_in; (void)out_size;
    const float* input    = (const float*)d_in[0];
    const float* original = (const float*)d_in[1];
    const float* wq    = (const float*)d_in[2];
    const float* bq    = (const float*)d_in[3];
    const float* wk    = (const float*)d_in[4];
    const float* bk    = (const float*)d_in[5];
    const float* wv    = (const float*)d_in[6];
    const float* bv    = (const float*)d_in[7];
    const float* gamma = (const float*)d_in[8];
    float* out = (float*)d_out;

    cudaFuncSetAttribute(attn_kernel, cudaFuncAttributeMaxDynamicSharedMemorySize, ATTN_SMEM);
    cudaFuncSetAttribute(v_proj_mma_kernel, cudaFuncAttributeMaxDynamicSharedMemorySize, VPROJ_SMEM);

    split_orig_kernel<<<dim3(HWDIM / 64, CD / 64, NB), 256>>>(original);
    split_wv_kernel<<<64, 256>>>(wv);
    qk_proj_kernel<<<dim3(HWDIM / 64, NB), 256>>>(input, wq, bq, wk, bk);
    v_proj_mma_kernel<<<dim3(HWDIM / 256, CD / 64, NB), 256, VPROJ_SMEM>>>(bv);
    attn_kernel<<<dim3(HWDIM / 64, NB), 256, ATTN_SMEM>>>(input, gamma, out);
}

// round 12
// speedup vs baseline: 4.1811x; 1.1627x over previous
#include <cuda_runtime.h>
#include <cuda_bf16.h>
#include <cuda_fp16.h>
#include <cstdint>

typedef unsigned long long u64;
typedef unsigned int       u32;

#define HWDIM 4096
#define CD    256
#define NB    4
#define NTILE 64
#define LOG2E 1.4426950408889634f

// ---------------- scratch (no allocations allowed) ----------------
__device__ __nv_bfloat16 g_qhl[(size_t)NB * HWDIM * 64];   // [b][n][Qh(32)|Ql(32)] (Q pre-scaled by log2e)
__device__ __nv_bfloat16 g_khl[(size_t)NB * HWDIM * 64];   // [b][n][Kh|Kl]
__device__ __half        g_vh[(size_t)NB * CD * HWDIM];    // [b][c][n]  fp16 V
__device__ __nv_bfloat16 g_oh[(size_t)NB * HWDIM * CD];    // [b][n][c]  orig hi
__device__ __nv_bfloat16 g_ol[(size_t)NB * HWDIM * CD];    // [b][n][c]  orig lo
__device__ __nv_bfloat16 g_wvh[CD * CD];                   // [c][k]
__device__ __nv_bfloat16 g_wvl[CD * CD];

// ---------------- helpers ----------------
__device__ __forceinline__ u32 saddr(const void* p) { return (u32)__cvta_generic_to_shared(p); }
__device__ __forceinline__ void cp16(u32 dst, const void* src) {
    asm volatile("cp.async.cg.shared.global [%0], [%1], 16;" :: "r"(dst), "l"(src));
}
__device__ __forceinline__ void cp_commit() { asm volatile("cp.async.commit_group;" ::: "memory"); }
__device__ __forceinline__ void cp_wait0()  { asm volatile("cp.async.wait_group 0;" ::: "memory"); }

__device__ __forceinline__ u32 bf2(float lo, float hi) {
    u32 r; asm("cvt.rn.bf16x2.f32 %0, %1, %2;" : "=r"(r) : "f"(hi), "f"(lo)); return r;
}
__device__ __forceinline__ u32 f162(float lo, float hi) {
    u32 r; asm("cvt.rn.f16x2.f32 %0, %1, %2;" : "=r"(r) : "f"(hi), "f"(lo)); return r;
}
__device__ __forceinline__ u64 pk64(u32 lo, u32 hi) {
    u64 r; asm("mov.b64 %0, {%1, %2};" : "=l"(r) : "r"(lo), "r"(hi)); return r;
}
__device__ __forceinline__ float lo16f(u32 h) { return __uint_as_float(h << 16); }
__device__ __forceinline__ float hi16f(u32 h) { return __uint_as_float(h & 0xFFFF0000u); }
__device__ __forceinline__ float f2lo(u64 v) { return __uint_as_float((u32)v); }
__device__ __forceinline__ float f2hi(u64 v) { return __uint_as_float((u32)(v >> 32)); }
__device__ __forceinline__ u64 ffma2(u64 a, u64 b, u64 c) {
    u64 d; asm("fma.rn.f32x2 %0, %1, %2, %3;" : "=l"(d) : "l"(a), "l"(b), "l"(c)); return d;
}
__device__ __forceinline__ u64 pack2(float lo, float hi) {
    u64 d; asm("mov.b64 %0, {%1, %2};" : "=l"(d) : "f"(lo), "f"(hi)); return d;
}
__device__ __forceinline__ float ex2f(float x) {
    float r; asm("ex2.approx.f32 %0, %1;" : "=f"(r) : "f"(x)); return r;
}

#define LDSM4(r, a) \
    asm volatile("ldmatrix.sync.aligned.m8n8.x4.shared.b16 {%0,%1,%2,%3}, [%4];" \
        : "=r"((r)[0]), "=r"((r)[1]), "=r"((r)[2]), "=r"((r)[3]) : "r"(a))

#define MMA(d, a, b0_, b1_) \
    asm volatile("mma.sync.aligned.m16n8k16.row.col.f32.bf16.bf16.f32 " \
        "{%0,%1,%2,%3}, {%4,%5,%6,%7}, {%8,%9}, {%0,%1,%2,%3};" \
        : "+f"((d)[0]), "+f"((d)[1]), "+f"((d)[2]), "+f"((d)[3]) \
        : "r"((a)[0]), "r"((a)[1]), "r"((a)[2]), "r"((a)[3]), "r"(b0_), "r"(b1_))

#define MMAH(d, a, b0_, b1_) \
    asm volatile("mma.sync.aligned.m16n8k16.row.col.f32.f16.f16.f32 " \
        "{%0,%1,%2,%3}, {%4,%5,%6,%7}, {%8,%9}, {%0,%1,%2,%3};" \
        : "+f"((d)[0]), "+f"((d)[1]), "+f"((d)[2]), "+f"((d)[3]) \
        : "r"((a)[0]), "r"((a)[1]), "r"((a)[2]), "r"((a)[3]), "r"(b0_), "r"(b1_))

// =====================================================================
// Split+transpose: orig [b][c][n] fp32 -> g_oh/g_ol [b][n][c] bf16
// =====================================================================
__global__ __launch_bounds__(256) void split_orig_kernel(const float* __restrict__ orig)
{
    __shared__ float xs[64][65];
    const int tid = threadIdx.x;
    const int b = blockIdx.z;
    const int c0 = blockIdx.y * 64;
    const int n0 = blockIdx.x * 64;
    const float* ob = orig + ((size_t)b * CD + c0) * HWDIM + n0;
#pragma unroll
    for (int it = 0; it < 16; ++it) {
        int idx = tid + it * 256;
        int cc = idx >> 6, nn = idx & 63;
        xs[cc][nn] = ob[(size_t)cc * HWDIM + nn];
    }
    __syncthreads();
#pragma unroll
    for (int it = 0; it < 4; ++it) {
        int idx = tid + it * 256;
        int n = idx >> 4, c4 = (idx & 15) * 4;
        float y0 = xs[c4][n], y1 = xs[c4 + 1][n], y2 = xs[c4 + 2][n], y3 = xs[c4 + 3][n];
        u32 h01 = bf2(y0, y1), h23 = bf2(y2, y3);
        u32 l01 = bf2(y0 - lo16f(h01), y1 - hi16f(h01));
        u32 l23 = bf2(y2 - lo16f(h23), y3 - hi16f(h23));
        size_t off = ((size_t)b * HWDIM + n0 + n) * CD + c0 + c4;
        *(u64*)(g_oh + off) = pk64(h01, h23);
        *(u64*)(g_ol + off) = pk64(l01, l23);
    }
}

__global__ __launch_bounds__(256) void split_wv_kernel(const float* __restrict__ wv)
{
    int i = (blockIdx.x * 256 + threadIdx.x) * 4;
    float y0 = wv[i], y1 = wv[i + 1], y2 = wv[i + 2], y3 = wv[i + 3];
    u32 h01 = bf2(y0, y1), h23 = bf2(y2, y3);
    u32 l01 = bf2(y0 - lo16f(h01), y1 - hi16f(h01));
    u32 l23 = bf2(y2 - lo16f(h23), y3 - hi16f(h23));
    *(u64*)(g_wvh + i) = pk64(h01, h23);
    *(u64*)(g_wvl + i) = pk64(l01, l23);
}

// =====================================================================
// QK projection (fp32 FFMA2) -> bf16 hi/lo splits; Q scaled by log2e.
// =====================================================================
__global__ __launch_bounds__(256) void qk_proj_kernel(
    const float* __restrict__ x,
    const float* __restrict__ wq, const float* __restrict__ bq,
    const float* __restrict__ wk, const float* __restrict__ bk)
{
    __shared__ float xs[64][65];
    __shared__ float ws[64][66];
    const int tid = threadIdx.x;
    const int b = blockIdx.y;
    const int n0 = blockIdx.x * 64;
    const int tx = tid & 15, ty = tid >> 4;

    u64 acc[4][2];
#pragma unroll
    for (int i = 0; i < 4; ++i) { acc[i][0] = 0ull; acc[i][1] = 0ull; }

    const float* xb = x + (size_t)b * CD * HWDIM;

    for (int c0 = 0; c0 < CD; c0 += 64) {
        __syncthreads();
#pragma unroll
        for (int it = 0; it < 16; ++it) {
            int idx = tid + it * 256;
            int cc = idx >> 6, nn = idx & 63;
            xs[cc][nn] = xb[(size_t)(c0 + cc) * HWDIM + n0 + nn];
        }
#pragma unroll
        for (int it = 0; it < 16; ++it) {
            int idx = tid + it * 256;
            int o = idx >> 6, cc = idx & 63;
            ws[cc][o] = (o < 32) ? wq[o * CD + c0 + cc] : wk[(o - 32) * CD + c0 + cc];
        }
        __syncthreads();
#pragma unroll 8
        for (int kk = 0; kk < 64; ++kk) {
            u64 a0 = *(const u64*)&ws[kk][ty * 4];
            u64 a1 = *(const u64*)&ws[kk][ty * 4 + 2];
#pragma unroll
            for (int i = 0; i < 4; ++i) {
                float bv2 = xs[kk][tx * 4 + i];
                u64 bd = pack2(bv2, bv2);
                acc[i][0] = ffma2(a0, bd, acc[i][0]);
                acc[i][1] = ffma2(a1, bd, acc[i][1]);
            }
        }
    }
    const int og = ty * 4;
    float bb0, bb1, bb2, bb3;
    if (ty < 8) { bb0 = bq[og]; bb1 = bq[og + 1]; bb2 = bq[og + 2]; bb3 = bq[og + 3]; }
    else        { bb0 = bk[og - 32]; bb1 = bk[og - 31]; bb2 = bk[og - 30]; bb3 = bk[og - 29]; }
    __nv_bfloat16* arr = (ty < 8) ? g_qhl : g_khl;
    const int ol = (ty < 8) ? og : og - 32;
    const float sc = (ty < 8) ? LOG2E : 1.0f;
#pragma unroll
    for (int i = 0; i < 4; ++i) {
        int n = n0 + tx * 4 + i;
        float f0 = (f2lo(acc[i][0]) + bb0) * sc;
        float f1 = (f2hi(acc[i][0]) + bb1) * sc;
        float f2 = (f2lo(acc[i][1]) + bb2) * sc;
        float f3 = (f2hi(acc[i][1]) + bb3) * sc;
        u32 h01 = bf2(f0, f1), h23 = bf2(f2, f3);
        u32 l01 = bf2(f0 - lo16f(h01), f1 - hi16f(h01));
        u32 l23 = bf2(f2 - lo16f(h23), f3 - hi16f(h23));
        __nv_bfloat16* base = arr + ((size_t)b * HWDIM + n) * 64 + ol;
        *(u64*)base        = pk64(h01, h23);
        *(u64*)(base + 32) = pk64(l01, l23);
    }
}

// =====================================================================
// V projection via mma.sync bf16 (3-term): g_vh[b][c][n] = wv·orig + bv
// Output packed fp16.
// =====================================================================
#define VSWH 0u
#define VSWL 33792u
#define VSB  67584u
#define VSBB 73728u
#define VSXL 36864u
#define VPROJ_SMEM 215040

__global__ __launch_bounds__(256, 1) void v_proj_mma_kernel(const float* __restrict__ bv)
{
    extern __shared__ char smem_raw[];
    const u32 sb = saddr(smem_raw);
    const int tid = threadIdx.x;
    const int lane = tid & 31;
    const int warp = tid >> 5;
    const int b = blockIdx.z;
    const int ctile = blockIdx.y * 64;
    const int n0 = blockIdx.x * 256;
    const int rm = warp >> 1;
    const int nh = warp & 1;

    const __nv_bfloat16* xh = g_oh + (size_t)b * HWDIM * CD;
    const __nv_bfloat16* xl = g_ol + (size_t)b * HWDIM * CD;

#pragma unroll
    for (int it = 0; it < 8; ++it) {
        int idx = tid + it * 256;
        int r = idx >> 5, ch = idx & 31;
        cp16(sb + VSWH + (u32)(r * 528 + ch * 16), g_wvh + (ctile + r) * CD + ch * 8);
        cp16(sb + VSWL + (u32)(r * 528 + ch * 16), g_wvl + (ctile + r) * CD + ch * 8);
    }
#pragma unroll
    for (int it = 0; it < 8; ++it) {
        int idx = tid + it * 256;
        int r = idx >> 3, ch = idx & 7;
        u32 doff = (u32)(r * 144 + ch * 16);
        size_t soff = (size_t)(n0 + r) * CD + ch * 8;
        cp16(sb + VSB + doff, xh + soff);
        cp16(sb + VSB + VSXL + doff, xl + soff);
    }
    cp_commit();

    float o[16][4];
#pragma unroll
    for (int i = 0; i < 16; ++i) { o[i][0] = 0.f; o[i][1] = 0.f; o[i][2] = 0.f; o[i][3] = 0.f; }

    for (int ks = 0; ks < 4; ++ks) {
        const int buf = ks & 1;
        cp_wait0();
        __syncthreads();
        if (ks < 3) {
#pragma unroll
            for (int it = 0; it < 8; ++it) {
                int idx = tid + it * 256;
                int r = idx >> 3, ch = idx & 7;
                u32 doff = (u32)((buf ^ 1) * VSBB + r * 144 + ch * 16);
                size_t soff = (size_t)(n0 + r) * CD + (ks + 1) * 64 + ch * 8;
                cp16(sb + VSB + doff, xh + soff);
                cp16(sb + VSB + VSXL + doff, xl + soff);
            }
            cp_commit();
        }

        u32 wh[4][4], wl[4][4];
        {
            u32 abase = sb + (u32)((rm * 16 + (lane & 15)) * 528 + ks * 128 + (lane >> 4) * 16);
#pragma unroll
            for (int j = 0; j < 4; ++j) {
                LDSM4(wh[j], abase + VSWH + (u32)(j * 32));
                LDSM4(wl[j], abase + VSWL + (u32)(j * 32));
            }
        }
        const u32 vbb = sb + VSB + (u32)buf * VSBB + (u32)((nh * 128 + (lane & 7)) * 144 + (lane >> 3) * 16);
#pragma unroll
        for (int nt = 0; nt < 16; ++nt) {
            u32 xh0[4], xh1[4], xl0[4], xl1[4];
            u32 rb = vbb + (u32)(nt * 1152);
            LDSM4(xh0, rb);
            LDSM4(xh1, rb + 64);
            LDSM4(xl0, rb + VSXL);
            LDSM4(xl1, rb + VSXL + 64);
            MMA(o[nt], wh[0], xh0[0], xh0[1]);
            MMA(o[nt], wh[1], xh0[2], xh0[3]);
            MMA(o[nt], wh[2], xh1[0], xh1[1]);
            MMA(o[nt], wh[3], xh1[2], xh1[3]);
            MMA(o[nt], wh[0], xl0[0], xl0[1]);
            MMA(o[nt], wh[1], xl0[2], xl0[3]);
            MMA(o[nt], wh[2], xl1[0], xl1[1]);
            MMA(o[nt], wh[3], xl1[2], xl1[3]);
            MMA(o[nt], wl[0], xh0[0], xh0[1]);
            MMA(o[nt], wl[1], xh0[2], xh0[3]);
            MMA(o[nt], wl[2], xh1[0], xh1[1]);
            MMA(o[nt], wl[3], xh1[2], xh1[3]);
        }
    }

    const int r0 = rm * 16 + (lane >> 2);
    const float b0 = bv[ctile + r0];
    const float b1 = bv[ctile + r0 + 8];
    __half* v0 = g_vh + ((size_t)b * CD + ctile + r0) * HWDIM + n0 + nh * 128 + 2 * (lane & 3);
    __half* v1 = v0 + (size_t)8 * HWDIM;
#pragma unroll
    for (int nt = 0; nt < 16; ++nt) {
        *(u32*)(v0 + nt * 8) = f162(o[nt][0] + b0, o[nt][1] + b0);
        *(u32*)(v1 + nt * 8) = f162(o[nt][2] + b1, o[nt][3] + b1);
    }
}

// =====================================================================
// Flash attention: bf16 3-term MMA1, online softmax (running row max),
// fp16 P (single) x fp16 V -> MMA2 halved (64 MMAs/tile).
// 256 threads (8 warps); warp = 16 q x 128 c; CTA = 64 q; 2 CTAs/SM.
// =====================================================================
#define SQ   0u
#define SK   9216u
#define SKB  9216u
#define SV   27648u
#define SVB  36864u
#define LSOFF 101376u
#define ATTN_SMEM 101632

__device__ __forceinline__ void load_kv_tile(u32 sb, int buf, int j0, int tid,
    const __nv_bfloat16* kg, const __half* vh)
{
    u32 kd = sb + SK + (u32)buf * SKB;
#pragma unroll
    for (int i = 0; i < 2; ++i) {
        int idx = tid + i * 256;
        int r = idx >> 3, c = idx & 7;
        cp16(kd + (u32)(r * 144 + c * 16), kg + (size_t)(j0 + r) * 64 + c * 8);
    }
    u32 vb = sb + SV + (u32)buf * SVB;
#pragma unroll
    for (int i = 0; i < 8; ++i) {
        int idx = tid + i * 256;
        int r = idx >> 3, c = idx & 7;
        cp16(vb + (u32)(r * 144 + c * 16), vh + (size_t)r * HWDIM + j0 + c * 8);
    }
}

__global__ __launch_bounds__(256, 2) void attn_kernel(
    const float* __restrict__ inp,
    const float* __restrict__ gamma_p,
    float* __restrict__ out)
{
    extern __shared__ char smem_raw[];
    const u32 sb = saddr(smem_raw);
    const int tid = threadIdx.x;
    const int lane = tid & 31;
    const int warp = tid >> 5;
    const int b = blockIdx.y;
    const int n0 = blockIdx.x * 64;
    const int q0 = (warp >> 1) * 16;
    const int c0 = (warp & 1) * 128;

    const __nv_bfloat16* qg = g_qhl + ((size_t)b * HWDIM + n0) * 64;
    const __nv_bfloat16* kg = g_khl + (size_t)b * HWDIM * 64;
    const __half* vh = g_vh + (size_t)b * CD * HWDIM;

#pragma unroll
    for (int i = 0; i < 2; ++i) {
        int idx = tid + i * 256;
        int r = idx >> 3, c = idx & 7;
        cp16(sb + SQ + (u32)(r * 144 + c * 16), qg + (size_t)r * 64 + c * 8);
    }
    load_kv_tile(sb, 0, 0, tid, kg, vh);
    cp_commit();
    cp_wait0();
    __syncthreads();

    u32 qh[2][4], ql[2][4];
    {
        u32 base = sb + SQ + (u32)((q0 + (lane & 15)) * 144 + (lane >> 4) * 16);
        LDSM4(qh[0], base);
        LDSM4(qh[1], base + 32);
        LDSM4(ql[0], base + 64);
        LDSM4(ql[1], base + 96);
    }

    float o[16][4];
#pragma unroll
    for (int i = 0; i < 16; ++i) { o[i][0] = 0.f; o[i][1] = 0.f; o[i][2] = 0.f; o[i][3] = 0.f; }
    float lr0 = 0.f, lr1 = 0.f;
    float m0 = -1e30f, m1 = -1e30f;

    for (int t = 0; t < NTILE; ++t) {
        const int buf = t & 1;
        if (t) cp_wait0();
        __syncthreads();
        if (t + 1 < NTILE) { load_kv_tile(sb, buf ^ 1, (t + 1) * 64, tid, kg, vh); cp_commit(); }

        const u32 kbase = sb + SK + (u32)buf * SKB + (u32)((lane & 7) * 144 + (lane >> 3) * 16);
        const u32 vbb = sb + SV + (u32)buf * SVB + (u32)((c0 + (lane & 7)) * 144 + (lane >> 3) * 16);

#pragma unroll
        for (int h = 0; h < 2; ++h) {
            // ---- MMA1 (bf16 3-term) for j half: 24 MMAs ----
            float st[4][4];
#pragma unroll
            for (int n4 = 0; n4 < 4; ++n4) {
                int nt = h * 4 + n4;
                u32 bh[4], bl[4];
                LDSM4(bh, kbase + (u32)(nt * 1152));
                LDSM4(bl, kbase + (u32)(nt * 1152) + 64);
                st[n4][0] = 0.f; st[n4][1] = 0.f; st[n4][2] = 0.f; st[n4][3] = 0.f;
                MMA(st[n4], qh[0], bh[0], bh[1]);
                MMA(st[n4], qh[1], bh[2], bh[3]);
                MMA(st[n4], qh[0], bl[0], bl[1]);
                MMA(st[n4], qh[1], bl[2], bl[3]);
                MMA(st[n4], ql[0], bh[0], bh[1]);
                MMA(st[n4], ql[1], bh[2], bh[3]);
            }
            // ---- running max ----
            float mx0 = fmaxf(fmaxf(st[0][0], st[0][1]), fmaxf(st[1][0], st[1][1]));
            mx0 = fmaxf(mx0, fmaxf(fmaxf(st[2][0], st[2][1]), fmaxf(st[3][0], st[3][1])));
            float mx1 = fmaxf(fmaxf(st[0][2], st[0][3]), fmaxf(st[1][2], st[1][3]));
            mx1 = fmaxf(mx1, fmaxf(fmaxf(st[2][2], st[2][3]), fmaxf(st[3][2], st[3][3])));
            mx0 = fmaxf(mx0, __shfl_xor_sync(0xffffffffu, mx0, 1));
            mx0 = fmaxf(mx0, __shfl_xor_sync(0xffffffffu, mx0, 2));
            mx1 = fmaxf(mx1, __shfl_xor_sync(0xffffffffu, mx1, 1));
            mx1 = fmaxf(mx1, __shfl_xor_sync(0xffffffffu, mx1, 2));
            float mA = fmaxf(m0, mx0), mB = fmaxf(m1, mx1);
            if (__any_sync(0xffffffffu, (mA > m0) || (mB > m1))) {
                float a0 = ex2f(m0 - mA), a1 = ex2f(m1 - mB);
                lr0 *= a0; lr1 *= a1;
#pragma unroll
                for (int i = 0; i < 16; ++i) {
                    o[i][0] *= a0; o[i][1] *= a0; o[i][2] *= a1; o[i][3] *= a1;
                }
            }
            m0 = mA; m1 = mB;
            // ---- exp + fp16 pack (C-frag -> A-frag identity) ----
            u32 ph[2][4];
#pragma unroll
            for (int n4 = 0; n4 < 4; ++n4) {
                float p0 = ex2f(st[n4][0] - m0);
                float p1 = ex2f(st[n4][1] - m0);
                float p2 = ex2f(st[n4][2] - m1);
                float p3 = ex2f(st[n4][3] - m1);
                lr0 += p0 + p1;
                lr1 += p2 + p3;
                int ks = n4 >> 1, hf = (n4 & 1) * 2;
                ph[ks][hf]     = f162(p0, p1);
                ph[ks][hf + 1] = f162(p2, p3);
            }
            // ---- MMA2 (fp16): O += P·Vh for this j half: 32 MMAs ----
#pragma unroll
            for (int nt = 0; nt < 16; ++nt) {
                u32 vf[4];
                LDSM4(vf, vbb + (u32)(nt * 1152) + (u32)(h * 64));
                MMAH(o[nt], ph[0], vf[0], vf[1]);
                MMAH(o[nt], ph[1], vf[2], vf[3]);
            }
        }
    }

    // ---- epilogue ----
    lr0 += __shfl_xor_sync(0xffffffffu, lr0, 1);
    lr0 += __shfl_xor_sync(0xffffffffu, lr0, 2);
    lr1 += __shfl_xor_sync(0xffffffffu, lr1, 1);
    lr1 += __shfl_xor_sync(0xffffffffu, lr1, 2);
    float* ls = (float*)(smem_raw + LSOFF);
    if ((warp & 1) == 0 && (lane & 3) == 0) {
        ls[q0 + (lane >> 2)]     = lr0;
        ls[q0 + 8 + (lane >> 2)] = lr1;
    }
    __syncthreads();

    float* Os = (float*)smem_raw;
    if (tid < 64) ls[tid] = gamma_p[0] / ls[tid];
#pragma unroll
    for (int nt = 0; nt < 16; ++nt) {
        int cc = c0 + 8 * nt + 2 * (lane & 3);
        int qq = q0 + (lane >> 2);
        Os[cc * 68 + qq]            = o[nt][0];
        Os[(cc + 1) * 68 + qq]      = o[nt][1];
        Os[cc * 68 + qq + 8]        = o[nt][2];
        Os[(cc + 1) * 68 + qq + 8]  = o[nt][3];
    }
    __syncthreads();

    const float* ib = inp + (size_t)b * CD * HWDIM + n0;
    float* ob = out + (size_t)b * CD * HWDIM + n0;
#pragma unroll 4
    for (int it = 0; it < 64; ++it) {
        int idx = tid + it * 256;
        int c = idx >> 6, q = idx & 63;
        ob[(size_t)c * HWDIM + q] = Os[c * 68 + q] * ls[q] + ib[(size_t)c * HWDIM + q];
    }
}

// =====================================================================
extern "C" void kernel_launch(void* const* d_in, const int* in_sizes, int n_in,
                              void* d_out, int out_size)
{
    (void)in_sizes; (void)n_in; (void)out_size;
    const float* input    = (const float*)d_in[0];
    const float* original = (const float*)d_in[1];
    const float* wq    = (const float*)d_in[2];
    const float* bq    = (const float*)d_in[3];
    const float* wk    = (const float*)d_in[4];
    const float* bk    = (const float*)d_in[5];
    const float* wv    = (const float*)d_in[6];
    const float* bv    = (const float*)d_in[7];
    const float* gamma = (const float*)d_in[8];
    float* out = (float*)d_out;

    cudaFuncSetAttribute(attn_kernel, cudaFuncAttributeMaxDynamicSharedMemorySize, ATTN_SMEM);
    cudaFuncSetAttribute(v_proj_mma_kernel, cudaFuncAttributeMaxDynamicSharedMemorySize, VPROJ_SMEM);

    split_orig_kernel<<<dim3(HWDIM / 64, CD / 64, NB), 256>>>(original);
    split_wv_kernel<<<64, 256>>>(wv);
    qk_proj_kernel<<<dim3(HWDIM / 64, NB), 256>>>(input, wq, bq, wk, bk);
    v_proj_mma_kernel<<<dim3(HWDIM / 256, CD / 64, NB), 256, VPROJ_SMEM>>>(bv);
    attn_kernel<<<dim3(HWDIM / 64, NB), 256, ATTN_SMEM>>>(input, gamma, out);
}

// round 16
// speedup vs baseline: 4.8836x; 1.1680x over previous
#include <cuda_runtime.h>
#include <cuda_bf16.h>
#include <cuda_fp16.h>
#include <cstdint>

typedef unsigned long long u64;
typedef unsigned int       u32;

#define HWDIM 4096
#define CD    256
#define NB    4
#define NTILE 64
#define LOG2E 1.4426950408889634f

// ---------------- scratch (no allocations allowed) ----------------
__device__ __nv_bfloat16 g_qhl[(size_t)NB * HWDIM * 64];   // [b][n][Qh(32)|Ql(32)] (Q pre-scaled by log2e)
__device__ __nv_bfloat16 g_khl[(size_t)NB * HWDIM * 64];   // [b][n][Kh|Kl]
__device__ __half        g_vh[(size_t)NB * CD * HWDIM];    // [b][c][n]  fp16 V
__device__ __nv_bfloat16 g_oh[(size_t)NB * HWDIM * CD];    // [b][n][c]  orig hi
__device__ __nv_bfloat16 g_ol[(size_t)NB * HWDIM * CD];    // [b][n][c]  orig lo
__device__ __nv_bfloat16 g_wvh[CD * CD];                   // [c][k]
__device__ __nv_bfloat16 g_wvl[CD * CD];

// ---------------- helpers ----------------
__device__ __forceinline__ u32 saddr(const void* p) { return (u32)__cvta_generic_to_shared(p); }
__device__ __forceinline__ void cp16(u32 dst, const void* src) {
    asm volatile("cp.async.cg.shared.global [%0], [%1], 16;" :: "r"(dst), "l"(src));
}
__device__ __forceinline__ void cp_commit() { asm volatile("cp.async.commit_group;" ::: "memory"); }
__device__ __forceinline__ void cp_wait0()  { asm volatile("cp.async.wait_group 0;" ::: "memory"); }

__device__ __forceinline__ u32 bf2(float lo, float hi) {
    u32 r; asm("cvt.rn.bf16x2.f32 %0, %1, %2;" : "=r"(r) : "f"(hi), "f"(lo)); return r;
}
__device__ __forceinline__ u32 f162(float lo, float hi) {
    u32 r; asm("cvt.rn.f16x2.f32 %0, %1, %2;" : "=r"(r) : "f"(hi), "f"(lo)); return r;
}
__device__ __forceinline__ u64 pk64(u32 lo, u32 hi) {
    u64 r; asm("mov.b64 %0, {%1, %2};" : "=l"(r) : "r"(lo), "r"(hi)); return r;
}
__device__ __forceinline__ float lo16f(u32 h) { return __uint_as_float(h << 16); }
__device__ __forceinline__ float hi16f(u32 h) { return __uint_as_float(h & 0xFFFF0000u); }
__device__ __forceinline__ float f2lo(u64 v) { return __uint_as_float((u32)v); }
__device__ __forceinline__ float f2hi(u64 v) { return __uint_as_float((u32)(v >> 32)); }
__device__ __forceinline__ u64 ffma2(u64 a, u64 b, u64 c) {
    u64 d; asm("fma.rn.f32x2 %0, %1, %2, %3;" : "=l"(d) : "l"(a), "l"(b), "l"(c)); return d;
}
__device__ __forceinline__ u64 pack2(float lo, float hi) {
    u64 d; asm("mov.b64 %0, {%1, %2};" : "=l"(d) : "f"(lo), "f"(hi)); return d;
}
__device__ __forceinline__ float ex2f(float x) {
    float r; asm("ex2.approx.f32 %0, %1;" : "=f"(r) : "f"(x)); return r;
}
__device__ __forceinline__ void sts32(u32 a, u32 v) {
    asm volatile("st.shared.b32 [%0], %1;" :: "r"(a), "r"(v) : "memory");
}

#define LDSM4(r, a) \
    asm volatile("ldmatrix.sync.aligned.m8n8.x4.shared.b16 {%0,%1,%2,%3}, [%4];" \
        : "=r"((r)[0]), "=r"((r)[1]), "=r"((r)[2]), "=r"((r)[3]) : "r"(a))

#define MMA(d, a, b0_, b1_) \
    asm volatile("mma.sync.aligned.m16n8k16.row.col.f32.bf16.bf16.f32 " \
        "{%0,%1,%2,%3}, {%4,%5,%6,%7}, {%8,%9}, {%0,%1,%2,%3};" \
        : "+f"((d)[0]), "+f"((d)[1]), "+f"((d)[2]), "+f"((d)[3]) \
        : "r"((a)[0]), "r"((a)[1]), "r"((a)[2]), "r"((a)[3]), "r"(b0_), "r"(b1_))

#define MMAH(d, a, b0_, b1_) \
    asm volatile("mma.sync.aligned.m16n8k16.row.col.f32.f16.f16.f32 " \
        "{%0,%1,%2,%3}, {%4,%5,%6,%7}, {%8,%9}, {%0,%1,%2,%3};" \
        : "+f"((d)[0]), "+f"((d)[1]), "+f"((d)[2]), "+f"((d)[3]) \
        : "r"((a)[0]), "r"((a)[1]), "r"((a)[2]), "r"((a)[3]), "r"(b0_), "r"(b1_))

// =====================================================================
// Split+transpose: orig [b][c][n] fp32 -> g_oh/g_ol [b][n][c] bf16
// =====================================================================
__global__ __launch_bounds__(256) void split_orig_kernel(const float* __restrict__ orig)
{
    __shared__ float xs[64][65];
    const int tid = threadIdx.x;
    const int b = blockIdx.z;
    const int c0 = blockIdx.y * 64;
    const int n0 = blockIdx.x * 64;
    const float* ob = orig + ((size_t)b * CD + c0) * HWDIM + n0;
#pragma unroll
    for (int it = 0; it < 16; ++it) {
        int idx = tid + it * 256;
        int cc = idx >> 6, nn = idx & 63;
        xs[cc][nn] = ob[(size_t)cc * HWDIM + nn];
    }
    __syncthreads();
#pragma unroll
    for (int it = 0; it < 4; ++it) {
        int idx = tid + it * 256;
        int n = idx >> 4, c4 = (idx & 15) * 4;
        float y0 = xs[c4][n], y1 = xs[c4 + 1][n], y2 = xs[c4 + 2][n], y3 = xs[c4 + 3][n];
        u32 h01 = bf2(y0, y1), h23 = bf2(y2, y3);
        u32 l01 = bf2(y0 - lo16f(h01), y1 - hi16f(h01));
        u32 l23 = bf2(y2 - lo16f(h23), y3 - hi16f(h23));
        size_t off = ((size_t)b * HWDIM + n0 + n) * CD + c0 + c4;
        *(u64*)(g_oh + off) = pk64(h01, h23);
        *(u64*)(g_ol + off) = pk64(l01, l23);
    }
}

__global__ __launch_bounds__(256) void split_wv_kernel(const float* __restrict__ wv)
{
    int i = (blockIdx.x * 256 + threadIdx.x) * 4;
    float y0 = wv[i], y1 = wv[i + 1], y2 = wv[i + 2], y3 = wv[i + 3];
    u32 h01 = bf2(y0, y1), h23 = bf2(y2, y3);
    u32 l01 = bf2(y0 - lo16f(h01), y1 - hi16f(h01));
    u32 l23 = bf2(y2 - lo16f(h23), y3 - hi16f(h23));
    *(u64*)(g_wvh + i) = pk64(h01, h23);
    *(u64*)(g_wvl + i) = pk64(l01, l23);
}

// =====================================================================
// QK projection (fp32 FFMA2) -> bf16 hi/lo splits; Q scaled by log2e.
// =====================================================================
__global__ __launch_bounds__(256) void qk_proj_kernel(
    const float* __restrict__ x,
    const float* __restrict__ wq, const float* __restrict__ bq,
    const float* __restrict__ wk, const float* __restrict__ bk)
{
    __shared__ float xs[64][65];
    __shared__ float ws[64][66];
    const int tid = threadIdx.x;
    const int b = blockIdx.y;
    const int n0 = blockIdx.x * 64;
    const int tx = tid & 15, ty = tid >> 4;

    u64 acc[4][2];
#pragma unroll
    for (int i = 0; i < 4; ++i) { acc[i][0] = 0ull; acc[i][1] = 0ull; }

    const float* xb = x + (size_t)b * CD * HWDIM;

    for (int c0 = 0; c0 < CD; c0 += 64) {
        __syncthreads();
#pragma unroll
        for (int it = 0; it < 16; ++it) {
            int idx = tid + it * 256;
            int cc = idx >> 6, nn = idx & 63;
            xs[cc][nn] = xb[(size_t)(c0 + cc) * HWDIM + n0 + nn];
        }
#pragma unroll
        for (int it = 0; it < 16; ++it) {
            int idx = tid + it * 256;
            int o = idx >> 6, cc = idx & 63;
            ws[cc][o] = (o < 32) ? wq[o * CD + c0 + cc] : wk[(o - 32) * CD + c0 + cc];
        }
        __syncthreads();
#pragma unroll 8
        for (int kk = 0; kk < 64; ++kk) {
            u64 a0 = *(const u64*)&ws[kk][ty * 4];
            u64 a1 = *(const u64*)&ws[kk][ty * 4 + 2];
#pragma unroll
            for (int i = 0; i < 4; ++i) {
                float bv2 = xs[kk][tx * 4 + i];
                u64 bd = pack2(bv2, bv2);
                acc[i][0] = ffma2(a0, bd, acc[i][0]);
                acc[i][1] = ffma2(a1, bd, acc[i][1]);
            }
        }
    }
    const int og = ty * 4;
    float bb0, bb1, bb2, bb3;
    if (ty < 8) { bb0 = bq[og]; bb1 = bq[og + 1]; bb2 = bq[og + 2]; bb3 = bq[og + 3]; }
    else        { bb0 = bk[og - 32]; bb1 = bk[og - 31]; bb2 = bk[og - 30]; bb3 = bk[og - 29]; }
    __nv_bfloat16* arr = (ty < 8) ? g_qhl : g_khl;
    const int ol = (ty < 8) ? og : og - 32;
    const float sc = (ty < 8) ? LOG2E : 1.0f;
#pragma unroll
    for (int i = 0; i < 4; ++i) {
        int n = n0 + tx * 4 + i;
        float f0 = (f2lo(acc[i][0]) + bb0) * sc;
        float f1 = (f2hi(acc[i][0]) + bb1) * sc;
        float f2 = (f2lo(acc[i][1]) + bb2) * sc;
        float f3 = (f2hi(acc[i][1]) + bb3) * sc;
        u32 h01 = bf2(f0, f1), h23 = bf2(f2, f3);
        u32 l01 = bf2(f0 - lo16f(h01), f1 - hi16f(h01));
        u32 l23 = bf2(f2 - lo16f(h23), f3 - hi16f(h23));
        __nv_bfloat16* base = arr + ((size_t)b * HWDIM + n) * 64 + ol;
        *(u64*)base        = pk64(h01, h23);
        *(u64*)(base + 32) = pk64(l01, l23);
    }
}

// =====================================================================
// V projection via mma.sync bf16 (3-term) -> fp16 g_vh[b][c][n]
// =====================================================================
#define VSWH 0u
#define VSWL 33792u
#define VSB  67584u
#define VSBB 73728u
#define VSXL 36864u
#define VPROJ_SMEM 215040

__global__ __launch_bounds__(256, 1) void v_proj_mma_kernel(const float* __restrict__ bv)
{
    extern __shared__ char smem_raw[];
    const u32 sb = saddr(smem_raw);
    const int tid = threadIdx.x;
    const int lane = tid & 31;
    const int warp = tid >> 5;
    const int b = blockIdx.z;
    const int ctile = blockIdx.y * 64;
    const int n0 = blockIdx.x * 256;
    const int rm = warp >> 1;
    const int nh = warp & 1;

    const __nv_bfloat16* xh = g_oh + (size_t)b * HWDIM * CD;
    const __nv_bfloat16* xl = g_ol + (size_t)b * HWDIM * CD;

#pragma unroll
    for (int it = 0; it < 8; ++it) {
        int idx = tid + it * 256;
        int r = idx >> 5, ch = idx & 31;
        cp16(sb + VSWH + (u32)(r * 528 + ch * 16), g_wvh + (ctile + r) * CD + ch * 8);
        cp16(sb + VSWL + (u32)(r * 528 + ch * 16), g_wvl + (ctile + r) * CD + ch * 8);
    }
#pragma unroll
    for (int it = 0; it < 8; ++it) {
        int idx = tid + it * 256;
        int r = idx >> 3, ch = idx & 7;
        u32 doff = (u32)(r * 144 + ch * 16);
        size_t soff = (size_t)(n0 + r) * CD + ch * 8;
        cp16(sb + VSB + doff, xh + soff);
        cp16(sb + VSB + VSXL + doff, xl + soff);
    }
    cp_commit();

    float o[16][4];
#pragma unroll
    for (int i = 0; i < 16; ++i) { o[i][0] = 0.f; o[i][1] = 0.f; o[i][2] = 0.f; o[i][3] = 0.f; }

    for (int ks = 0; ks < 4; ++ks) {
        const int buf = ks & 1;
        cp_wait0();
        __syncthreads();
        if (ks < 3) {
#pragma unroll
            for (int it = 0; it < 8; ++it) {
                int idx = tid + it * 256;
                int r = idx >> 3, ch = idx & 7;
                u32 doff = (u32)((buf ^ 1) * VSBB + r * 144 + ch * 16);
                size_t soff = (size_t)(n0 + r) * CD + (ks + 1) * 64 + ch * 8;
                cp16(sb + VSB + doff, xh + soff);
                cp16(sb + VSB + VSXL + doff, xl + soff);
            }
            cp_commit();
        }

        u32 wh[4][4], wl[4][4];
        {
            u32 abase = sb + (u32)((rm * 16 + (lane & 15)) * 528 + ks * 128 + (lane >> 4) * 16);
#pragma unroll
            for (int j = 0; j < 4; ++j) {
                LDSM4(wh[j], abase + VSWH + (u32)(j * 32));
                LDSM4(wl[j], abase + VSWL + (u32)(j * 32));
            }
        }
        const u32 vbb = sb + VSB + (u32)buf * VSBB + (u32)((nh * 128 + (lane & 7)) * 144 + (lane >> 3) * 16);
#pragma unroll
        for (int nt = 0; nt < 16; ++nt) {
            u32 xh0[4], xh1[4], xl0[4], xl1[4];
            u32 rb = vbb + (u32)(nt * 1152);
            LDSM4(xh0, rb);
            LDSM4(xh1, rb + 64);
            LDSM4(xl0, rb + VSXL);
            LDSM4(xl1, rb + VSXL + 64);
            MMA(o[nt], wh[0], xh0[0], xh0[1]);
            MMA(o[nt], wh[1], xh0[2], xh0[3]);
            MMA(o[nt], wh[2], xh1[0], xh1[1]);
            MMA(o[nt], wh[3], xh1[2], xh1[3]);
            MMA(o[nt], wh[0], xl0[0], xl0[1]);
            MMA(o[nt], wh[1], xl0[2], xl0[3]);
            MMA(o[nt], wh[2], xl1[0], xl1[1]);
            MMA(o[nt], wh[3], xl1[2], xl1[3]);
            MMA(o[nt], wl[0], xh0[0], xh0[1]);
            MMA(o[nt], wl[1], xh0[2], xh0[3]);
            MMA(o[nt], wl[2], xh1[0], xh1[1]);
            MMA(o[nt], wl[3], xh1[2], xh1[3]);
        }
    }

    const int r0 = rm * 16 + (lane >> 2);
    const float b0 = bv[ctile + r0];
    const float b1 = bv[ctile + r0 + 8];
    __half* v0 = g_vh + ((size_t)b * CD + ctile + r0) * HWDIM + n0 + nh * 128 + 2 * (lane & 3);
    __half* v1 = v0 + (size_t)8 * HWDIM;
#pragma unroll
    for (int nt = 0; nt < 16; ++nt) {
        *(u32*)(v0 + nt * 8) = f162(o[nt][0] + b0, o[nt][1] + b0);
        *(u32*)(v1 + nt * 8) = f162(o[nt][2] + b1, o[nt][3] + b1);
    }
}

// =====================================================================
// Flash attention, warp-deduplicated S (R13 design, smem size FIXED):
// MMA1 roles: warp = (q-block, j-half): S[16q x 32j], 24 bf16 MMAs + 16 ex2.
// Row max exchanged via smem (exact online softmax), P stored fp16 in smem.
// MMA2 roles: warp = (q-block, c-half): O += P(ldsm) x V, 64 fp16 MMAs.
// 256 threads (8 warps); CTA = 64 q; grid (64, 4); 2 CTAs/SM.
// =====================================================================
#define SQ    0u
#define SK    9216u
#define SKB   9216u
#define SV    27648u
#define SVB   36864u
#define SP    101376u
#define MXOFF 110592u
#define LSOFF 111104u
#define ATTN_SMEM 112128    // LSOFF + 128*4  (R14 bug: was 111360 -> smem OOB)

__device__ __forceinline__ void load_kv_tile(u32 sb, int buf, int j0, int tid,
    const __nv_bfloat16* kg, const __half* vh)
{
    u32 kd = sb + SK + (u32)buf * SKB;
#pragma unroll
    for (int i = 0; i < 2; ++i) {
        int idx = tid + i * 256;
        int r = idx >> 3, c = idx & 7;
        cp16(kd + (u32)(r * 144 + c * 16), kg + (size_t)(j0 + r) * 64 + c * 8);
    }
    u32 vb = sb + SV + (u32)buf * SVB;
#pragma unroll
    for (int i = 0; i < 8; ++i) {
        int idx = tid + i * 256;
        int r = idx >> 3, c = idx & 7;
        cp16(vb + (u32)(r * 144 + c * 16), vh + (size_t)r * HWDIM + j0 + c * 8);
    }
}

__global__ __launch_bounds__(256, 2) void attn_kernel(
    const float* __restrict__ inp,
    const float* __restrict__ gamma_p,
    float* __restrict__ out)
{
    extern __shared__ char smem_raw[];
    const u32 sb = saddr(smem_raw);
    const int tid = threadIdx.x;
    const int lane = tid & 31;
    const int warp = tid >> 5;
    const int b = blockIdx.y;
    const int n0 = blockIdx.x * 64;
    const int qb = warp >> 1;
    const int q0 = qb * 16;
    const int jh = warp & 1;          // j-half for MMA1/softmax
    const int c0 = jh * 128;          // c-half for MMA2

    const __nv_bfloat16* qg = g_qhl + ((size_t)b * HWDIM + n0) * 64;
    const __nv_bfloat16* kg = g_khl + (size_t)b * HWDIM * 64;
    const __half* vh = g_vh + (size_t)b * CD * HWDIM;

#pragma unroll
    for (int i = 0; i < 2; ++i) {
        int idx = tid + i * 256;
        int r = idx >> 3, c = idx & 7;
        cp16(sb + SQ + (u32)(r * 144 + c * 16), qg + (size_t)r * 64 + c * 8);
    }
    load_kv_tile(sb, 0, 0, tid, kg, vh);
    cp_commit();
    cp_wait0();
    __syncthreads();

    u32 qh[2][4], ql[2][4];
    {
        u32 base = sb + SQ + (u32)((q0 + (lane & 15)) * 144 + (lane >> 4) * 16);
        LDSM4(qh[0], base);
        LDSM4(qh[1], base + 32);
        LDSM4(ql[0], base + 64);
        LDSM4(ql[1], base + 96);
    }

    float o[16][4];
#pragma unroll
    for (int i = 0; i < 16; ++i) { o[i][0] = 0.f; o[i][1] = 0.f; o[i][2] = 0.f; o[i][3] = 0.f; }
    float lr0 = 0.f, lr1 = 0.f;
    float m0 = -1e30f, m1 = -1e30f;

    float* mxs = (float*)(smem_raw + MXOFF);
    const int rr = lane >> 2;

    for (int t = 0; t < NTILE; ++t) {
        const int buf = t & 1;
        if (t) cp_wait0();
        __syncthreads();                 // KV(t) ready; P/mx consumed by all warps
        if (t + 1 < NTILE) { load_kv_tile(sb, buf ^ 1, (t + 1) * 64, tid, kg, vh); cp_commit(); }

        // ---- MMA1 (bf16 3-term) own (q-block, j-half): S[16 x 32] ----
        float st[4][4];
        const u32 kbase = sb + SK + (u32)buf * SKB + (u32)(jh * 4608)
                        + (u32)((lane & 7) * 144 + (lane >> 3) * 16);
#pragma unroll
        for (int n4 = 0; n4 < 4; ++n4) {
            u32 bh[4], bl[4];
            LDSM4(bh, kbase + (u32)(n4 * 1152));
            LDSM4(bl, kbase + (u32)(n4 * 1152) + 64);
            st[n4][0] = 0.f; st[n4][1] = 0.f; st[n4][2] = 0.f; st[n4][3] = 0.f;
            MMA(st[n4], qh[0], bh[0], bh[1]);
            MMA(st[n4], qh[1], bh[2], bh[3]);
            MMA(st[n4], qh[0], bl[0], bl[1]);
            MMA(st[n4], qh[1], bl[2], bl[3]);
            MMA(st[n4], ql[0], bh[0], bh[1]);
            MMA(st[n4], ql[1], bh[2], bh[3]);
        }
        // ---- warp-local row max over own 32 j, publish to smem ----
        float mx0 = fmaxf(fmaxf(st[0][0], st[0][1]), fmaxf(st[1][0], st[1][1]));
        mx0 = fmaxf(mx0, fmaxf(fmaxf(st[2][0], st[2][1]), fmaxf(st[3][0], st[3][1])));
        float mx1 = fmaxf(fmaxf(st[0][2], st[0][3]), fmaxf(st[1][2], st[1][3]));
        mx1 = fmaxf(mx1, fmaxf(fmaxf(st[2][2], st[2][3]), fmaxf(st[3][2], st[3][3])));
        mx0 = fmaxf(mx0, __shfl_xor_sync(0xffffffffu, mx0, 1));
        mx0 = fmaxf(mx0, __shfl_xor_sync(0xffffffffu, mx0, 2));
        mx1 = fmaxf(mx1, __shfl_xor_sync(0xffffffffu, mx1, 1));
        mx1 = fmaxf(mx1, __shfl_xor_sync(0xffffffffu, mx1, 2));
        if ((lane & 3) == 0) {
            mxs[jh * 64 + q0 + rr]     = mx0;
            mxs[jh * 64 + q0 + 8 + rr] = mx1;
        }
        __syncthreads();                 // maxima visible
        float mA = fmaxf(m0, fmaxf(mxs[q0 + rr],     mxs[64 + q0 + rr]));
        float mB = fmaxf(m1, fmaxf(mxs[q0 + 8 + rr], mxs[64 + q0 + 8 + rr]));
        if (__any_sync(0xffffffffu, (mA > m0) || (mB > m1))) {
            float a0 = ex2f(m0 - mA), a1 = ex2f(m1 - mB);
            lr0 *= a0; lr1 *= a1;
#pragma unroll
            for (int i = 0; i < 16; ++i) {
                o[i][0] *= a0; o[i][1] *= a0; o[i][2] *= a1; o[i][3] *= a1;
            }
        }
        m0 = mA; m1 = mB;
        // ---- exp + store P (fp16) to smem ----
        const u32 prow = sb + SP + (u32)((q0 + rr) * 144 + (jh * 32 + 2 * (lane & 3)) * 2);
#pragma unroll
        for (int n4 = 0; n4 < 4; ++n4) {
            float p0 = ex2f(st[n4][0] - m0);
            float p1 = ex2f(st[n4][1] - m0);
            float p2 = ex2f(st[n4][2] - m1);
            float p3 = ex2f(st[n4][3] - m1);
            lr0 += p0 + p1;
            lr1 += p2 + p3;
            sts32(prow + (u32)(n4 * 16),              f162(p0, p1));
            sts32(prow + (u32)(8 * 144 + n4 * 16),    f162(p2, p3));
        }
        __syncthreads();                 // P tile complete

        // ---- MMA2 (fp16): warp = (q-block, c-half); P via ldmatrix ----
        u32 pa[4][4];
        {
            const u32 pbase = sb + SP + (u32)((q0 + (lane & 15)) * 144 + (lane >> 4) * 16);
#pragma unroll
            for (int ks = 0; ks < 4; ++ks) LDSM4(pa[ks], pbase + (u32)(ks * 32));
        }
        const u32 vbb = sb + SV + (u32)buf * SVB + (u32)((c0 + (lane & 7)) * 144 + (lane >> 3) * 16);
#pragma unroll
        for (int nt = 0; nt < 16; ++nt) {
            u32 v0[4], v1[4];
            u32 rb = vbb + (u32)(nt * 1152);
            LDSM4(v0, rb);
            LDSM4(v1, rb + 64);
            MMAH(o[nt], pa[0], v0[0], v0[1]);
            MMAH(o[nt], pa[1], v0[2], v0[3]);
            MMAH(o[nt], pa[2], v1[0], v1[1]);
            MMAH(o[nt], pa[3], v1[2], v1[3]);
        }
    }

    // ---- epilogue ----
    lr0 += __shfl_xor_sync(0xffffffffu, lr0, 1);
    lr0 += __shfl_xor_sync(0xffffffffu, lr0, 2);
    lr1 += __shfl_xor_sync(0xffffffffu, lr1, 1);
    lr1 += __shfl_xor_sync(0xffffffffu, lr1, 2);
    float* ls = (float*)(smem_raw + LSOFF);
    if ((lane & 3) == 0) {
        ls[jh * 64 + q0 + rr]     = lr0;    // per-(j-half) partial l
        ls[jh * 64 + q0 + 8 + rr] = lr1;
    }
    __syncthreads();

    float* Os = (float*)smem_raw;
    if (tid < 64) ls[tid] = gamma_p[0] / (ls[tid] + ls[tid + 64]);
#pragma unroll
    for (int nt = 0; nt < 16; ++nt) {
        int cc = c0 + 8 * nt + 2 * (lane & 3);
        int qq = q0 + rr;
        Os[cc * 68 + qq]            = o[nt][0];
        Os[(cc + 1) * 68 + qq]      = o[nt][1];
        Os[cc * 68 + qq + 8]        = o[nt][2];
        Os[(cc + 1) * 68 + qq + 8]  = o[nt][3];
    }
    __syncthreads();

    const float* ib = inp + (size_t)b * CD * HWDIM + n0;
    float* ob = out + (size_t)b * CD * HWDIM + n0;
#pragma unroll 4
    for (int it = 0; it < 64; ++it) {
        int idx = tid + it * 256;
        int c = idx >> 6, q = idx & 63;
        ob[(size_t)c * HWDIM + q] = Os[c * 68 + q] * ls[q] + ib[(size_t)c * HWDIM + q];
    }
}

// =====================================================================
extern "C" void kernel_launch(void* const* d_in, const int* in_sizes, int n_in,
                              void* d_out, int out_size)
{
    (void)in_sizes; (void)n_in; (void)out_size;
    const float* input    = (const float*)d_in[0];
    const float* original = (const float*)d_in[1];
    const float* wq    = (const float*)d_in[2];
    const float* bq    = (const float*)d_in[3];
    const float* wk    = (const float*)d_in[4];
    const float* bk    = (const float*)d_in[5];
    const float* wv    = (const float*)d_in[6];
    const float* bv    = (const float*)d_in[7];
    const float* gamma = (const float*)d_in[8];
    float* out = (float*)d_out;

    cudaFuncSetAttribute(attn_kernel, cudaFuncAttributeMaxDynamicSharedMemorySize, ATTN_SMEM);
    cudaFuncSetAttribute(v_proj_mma_kernel, cudaFuncAttributeMaxDynamicSharedMemorySize, VPROJ_SMEM);

    split_orig_kernel<<<dim3(HWDIM / 64, CD / 64, NB), 256>>>(original);
    split_wv_kernel<<<64, 256>>>(wv);
    qk_proj_kernel<<<dim3(HWDIM / 64, NB), 256>>>(input, wq, bq, wk, bk);
    v_proj_mma_kernel<<<dim3(HWDIM / 256, CD / 64, NB), 256, VPROJ_SMEM>>>(bv);
    attn_kernel<<<dim3(HWDIM / 64, NB), 256, ATTN_SMEM>>>(input, gamma, out);
}